// round 4
// baseline (speedup 1.0000x reference)
#include <cuda_runtime.h>
#include <math.h>
#include <stdint.h>

// ---------------- problem constants ----------------
#define B_    4
#define S_    2048
#define H_    768
#define NH_   8
#define DH_   96
#define L_    128
#define ML_   15
#define LM_   1920      // L_*ML_
#define QKV_  2304      // 3*H_

// ---------------- scratch ----------------
__device__ float g_qkv  [(size_t)B_ * S_  * QKV_];
__device__ float g_attn [(size_t)B_ * LM_ * H_];
__device__ float g_oproj[(size_t)B_ * LM_ * H_];
__device__ float g_x    [(size_t)B_ * L_ * 2 * H_];
__device__ float g_y1   [(size_t)B_ * L_ * H_];
__device__ float g_y2   [(size_t)B_ * L_ * H_];

// ---------------- tf32 mma (raw f32 bits; HW truncates to tf32) ----------------
__device__ __forceinline__ void mma_tf32(float* d, const unsigned* a, const unsigned* b) {
    asm volatile(
        "mma.sync.aligned.m16n8k8.row.col.f32.tf32.tf32.f32 "
        "{%0,%1,%2,%3}, {%4,%5,%6,%7}, {%8,%9}, {%0,%1,%2,%3};"
        : "+f"(d[0]), "+f"(d[1]), "+f"(d[2]), "+f"(d[3])
        : "r"(a[0]), "r"(a[1]), "r"(a[2]), "r"(a[3]), "r"(b[0]), "r"(b[1]));
}

// ---------------- tf32 NT GEMM, register-prefetch double buffered ----------------
// C[M,N] = A[M,K] @ B[N,K]^T + bias.  M%128==0, N%128==0, K%32==0.
__global__ __launch_bounds__(256) void gemm_tf32_nt(
    const float* __restrict__ A, const float* __restrict__ Bw,
    const float* __restrict__ bias, float* __restrict__ C,
    int M, int N, int K)
{
    __shared__ unsigned As[4 * 8 * 128];
    __shared__ unsigned Bs[4 * 16 * 64];

    int tid = threadIdx.x;
    int warp = tid >> 5, lane = tid & 31;
    int warp_m = warp >> 1, warp_n = warp & 1;
    int m0 = blockIdx.y * 128, n0 = blockIdx.x * 128;

    float acc[2][8][4];
#pragma unroll
    for (int mi = 0; mi < 2; mi++)
#pragma unroll
        for (int ni = 0; ni < 8; ni++)
#pragma unroll
            for (int r = 0; r < 4; r++) acc[mi][ni][r] = 0.0f;

    int rowA[4], rowB[4], kqv[4];
#pragma unroll
    for (int i = 0; i < 4; i++) {
        int f = tid + i * 256;
        rowA[i] = f >> 3; rowB[i] = f >> 3; kqv[i] = f & 7;
    }

    float4 ra[4], rb[4];
#pragma unroll
    for (int i = 0; i < 4; i++) {
        ra[i] = *(const float4*)(A  + (size_t)(m0 + rowA[i]) * K + kqv[i] * 4);
        rb[i] = *(const float4*)(Bw + (size_t)(n0 + rowB[i]) * K + kqv[i] * 4);
    }

    for (int k0 = 0; k0 < K; k0 += 32) {
        __syncthreads();
        // ---- store prefetched slab to fragment-ordered smem ----
#pragma unroll
        for (int i = 0; i < 4; i++) {
            int row = rowA[i], kq = kqv[i];
            int mtile = row >> 4, r = row & 15, ktile = kq >> 1;
            int regb = (r >> 3) + ((kq & 1) << 1);
            unsigned* p = &As[((ktile * 8 + mtile) * 32 + (r & 7) * 4) * 4 + regb];
            p[0]  = __float_as_uint(ra[i].x);
            p[4]  = __float_as_uint(ra[i].y);
            p[8]  = __float_as_uint(ra[i].z);
            p[12] = __float_as_uint(ra[i].w);
            int ntile = row >> 3, ktB = kq >> 1, reg = kq & 1;
            unsigned* q = &Bs[(ktB * 16 + ntile) * 64 + (row & 7) * 8 + reg];
            q[0] = __float_as_uint(rb[i].x);
            q[2] = __float_as_uint(rb[i].y);
            q[4] = __float_as_uint(rb[i].z);
            q[6] = __float_as_uint(rb[i].w);
        }
        __syncthreads();
        // ---- issue prefetch of next slab (latency hidden under compute) ----
        if (k0 + 32 < K) {
#pragma unroll
            for (int i = 0; i < 4; i++) {
                ra[i] = *(const float4*)(A  + (size_t)(m0 + rowA[i]) * K + k0 + 32 + kqv[i] * 4);
                rb[i] = *(const float4*)(Bw + (size_t)(n0 + rowB[i]) * K + k0 + 32 + kqv[i] * 4);
            }
        }
        // ---- compute ----
#pragma unroll
        for (int ks = 0; ks < 4; ks++) {
            uint4 a[2];
            uint2 b[8];
#pragma unroll
            for (int mi = 0; mi < 2; mi++)
                a[mi] = *(const uint4*)&As[((ks * 8 + warp_m * 2 + mi) * 32 + lane) * 4];
#pragma unroll
            for (int ni = 0; ni < 8; ni++)
                b[ni] = *(const uint2*)&Bs[((ks * 16 + warp_n * 8 + ni) * 32 + lane) * 2];
#pragma unroll
            for (int mi = 0; mi < 2; mi++)
#pragma unroll
                for (int ni = 0; ni < 8; ni++)
                    mma_tf32(acc[mi][ni], (const unsigned*)&a[mi], (const unsigned*)&b[ni]);
        }
    }

    // ---- epilogue ----
#pragma unroll
    for (int mi = 0; mi < 2; mi++) {
        int row = m0 + warp_m * 32 + mi * 16 + (lane >> 2);
#pragma unroll
        for (int ni = 0; ni < 8; ni++) {
            int col = n0 + warp_n * 64 + ni * 8 + ((lane & 3) << 1);
            float b0 = bias ? bias[col] : 0.0f;
            float b1 = bias ? bias[col + 1] : 0.0f;
            float2 lo = make_float2(acc[mi][ni][0] + b0, acc[mi][ni][1] + b1);
            float2 hi = make_float2(acc[mi][ni][2] + b0, acc[mi][ni][3] + b1);
            *(float2*)(C + (size_t)row * N + col)       = lo;
            *(float2*)(C + (size_t)(row + 8) * N + col) = hi;
        }
    }
}

// ---------------- tf32 flash cross-attention, register-prefetch K/V ----------------
#define QT 32
#define KT 64
#define PSP 68
__global__ __launch_bounds__(128) void attn_kernel(
    const float* __restrict__ qkv,
    const int* __restrict__ line_starts,
    const int* __restrict__ ctx_len,
    float* __restrict__ out)
{
    // Qbuf: fragment-staged Q during prologue, then reused as Ps (scores).
    __shared__ unsigned Qbuf[12 * 2 * 128];          // 3072 words >= 32*68=2176
    __shared__ unsigned KVs[6144];
    __shared__ float m_s[QT], l_s[QT], fac_s[QT];
    float* Ps = (float*)Qbuf;

    int tid = threadIdx.x;
    int warp = tid >> 5, lane = tid & 31;
    int warp_m = warp >> 1;
    int warp_n = warp & 1;
    int b = blockIdx.z, h = blockIdx.y, q0 = blockIdx.x * QT;
    const float scale = 0.10206207261596577f; // 1/sqrt(96)

    // ---- prologue: gather Q tile -> fragment-order smem ----
#pragma unroll
    for (int i = 0; i < 6; i++) {
        int f = tid + i * 128;
        int row = f / 24, dq = f - row * 24;
        int d0 = dq * 4;
        int gq = q0 + row;
        int l = gq / ML_;
        int m = gq - l * ML_;
        int pos = line_starts[b * L_ + l] + m;
        pos = min(max(pos, 0), S_ - 1);
        float4 v = *(const float4*)(qkv + ((size_t)b * S_ + pos) * QKV_ + h * DH_ + d0);
        int mtile = row >> 4, r = row & 15, ktile = dq >> 1;
        int regb = (r >> 3) + ((dq & 1) << 1);
        unsigned* p = &Qbuf[(ktile * 2 + mtile) * 128 + ((r & 7) * 4) * 4 + regb];
        p[0]  = __float_as_uint(v.x * scale);
        p[4]  = __float_as_uint(v.y * scale);
        p[8]  = __float_as_uint(v.z * scale);
        p[12] = __float_as_uint(v.w * scale);
    }
    if (tid < QT) { m_s[tid] = -3e38f; l_s[tid] = 0.0f; }
    int ctx = ctx_len[b];
    __syncthreads();

    // Q fragments live in registers for the whole loop; Qbuf becomes Ps.
    uint4 qf[12];
#pragma unroll
    for (int ks = 0; ks < 12; ks++)
        qf[ks] = *(const uint4*)&Qbuf[(ks * 2 + warp_m) * 128 + lane * 4];

    float Oacc[6][4];
#pragma unroll
    for (int ni = 0; ni < 6; ni++)
#pragma unroll
        for (int r = 0; r < 4; r++) Oacc[ni][r] = 0.0f;

    int r0 = warp_m * 16 + (lane >> 2);

    // per-thread fill coordinates (12 x float4 covers 64 tokens x 96 dims)
    int tok_[12], dq_[12];
#pragma unroll
    for (int i = 0; i < 12; i++) {
        int f = tid + i * 128;
        tok_[i] = f / 24; dq_[i] = f - tok_[i] * 24;
    }

    // prefetch K chunk 0
    float4 rk[12];
#pragma unroll
    for (int i = 0; i < 12; i++)
        rk[i] = *(const float4*)(qkv + ((size_t)b * S_ + tok_[i]) * QKV_ + H_ + h * DH_ + dq_[i] * 4);

    for (int s0 = 0; s0 < S_; s0 += KT) {
        __syncthreads();   // KVs free (prev PV done); Qbuf reads done (chunk 0)
        // ---- store K chunk (B-matrix: n=token, k=dim) ----
#pragma unroll
        for (int i = 0; i < 12; i++) {
            int token = tok_[i], dq = dq_[i];
            int ktile = dq >> 1, ntile = token >> 3, reg = dq & 1;
            unsigned* p = &KVs[(ktile * 8 + ntile) * 64 + (token & 7) * 8 + reg];
            p[0] = __float_as_uint(rk[i].x);
            p[2] = __float_as_uint(rk[i].y);
            p[4] = __float_as_uint(rk[i].z);
            p[6] = __float_as_uint(rk[i].w);
        }
        __syncthreads();

        // ---- prefetch V of this chunk (consumed after softmax) ----
#pragma unroll
        for (int i = 0; i < 12; i++)
            rk[i] = *(const float4*)(qkv + ((size_t)b * S_ + s0 + tok_[i]) * QKV_ + 2 * H_ + h * DH_ + dq_[i] * 4);

        // ---- scores: warp computes 16(q) x 32(tok) ----
        float sacc[4][4];
#pragma unroll
        for (int ni = 0; ni < 4; ni++)
#pragma unroll
            for (int r = 0; r < 4; r++) sacc[ni][r] = 0.0f;
#pragma unroll
        for (int ks = 0; ks < 12; ks++) {
            uint2 kb[4];
#pragma unroll
            for (int ni = 0; ni < 4; ni++)
                kb[ni] = *(const uint2*)&KVs[((ks * 8 + warp_n * 4 + ni) * 32 + lane) * 2];
#pragma unroll
            for (int ni = 0; ni < 4; ni++)
                mma_tf32(sacc[ni], (const unsigned*)&qf[ks], (const unsigned*)&kb[ni]);
        }
#pragma unroll
        for (int ni = 0; ni < 4; ni++) {
            int cb = warp_n * 32 + ni * 8 + ((lane & 3) << 1);
            int s_g = s0 + cb;
            Ps[r0 * PSP + cb]           = (s_g     < ctx) ? sacc[ni][0] : -1e9f;
            Ps[r0 * PSP + cb + 1]       = (s_g + 1 < ctx) ? sacc[ni][1] : -1e9f;
            Ps[(r0 + 8) * PSP + cb]     = (s_g     < ctx) ? sacc[ni][2] : -1e9f;
            Ps[(r0 + 8) * PSP + cb + 1] = (s_g + 1 < ctx) ? sacc[ni][3] : -1e9f;
        }
        __syncthreads();   // Ps visible; K-region reads complete

        // ---- online softmax: one quad per query row ----
        {
            int row = tid >> 2, sub = tid & 3;
            float mx = -3e38f;
#pragma unroll
            for (int k = sub; k < KT; k += 4) mx = fmaxf(mx, Ps[row * PSP + k]);
            mx = fmaxf(mx, __shfl_xor_sync(0xffffffffu, mx, 1));
            mx = fmaxf(mx, __shfl_xor_sync(0xffffffffu, mx, 2));
            float mold = m_s[row];
            float mnew = fmaxf(mold, mx);
            float lsum = 0.0f;
#pragma unroll
            for (int k = sub; k < KT; k += 4) {
                float p = __expf(Ps[row * PSP + k] - mnew);
                Ps[row * PSP + k] = p;
                lsum += p;
            }
            lsum += __shfl_xor_sync(0xffffffffu, lsum, 1);
            lsum += __shfl_xor_sync(0xffffffffu, lsum, 2);
            if (sub == 0) {
                float fct = __expf(mold - mnew);
                m_s[row]   = mnew;
                l_s[row]   = l_s[row] * fct + lsum;
                fac_s[row] = fct;
            }
        }

        // ---- store V chunk (prefetched; overwrite K region) ----
#pragma unroll
        for (int i = 0; i < 12; i++) {
            int token = tok_[i], dq = dq_[i];
            int d0 = dq * 4;
            int ktile = token >> 3, ntile = dq >> 1;
            int reg = (token & 4) >> 2;
            int laneb = (d0 & 7) * 4 + (token & 3);
            unsigned* p = &KVs[(ktile * 12 + ntile) * 64 + laneb * 2 + reg];
            p[0]  = __float_as_uint(rk[i].x);
            p[8]  = __float_as_uint(rk[i].y);
            p[16] = __float_as_uint(rk[i].z);
            p[24] = __float_as_uint(rk[i].w);
        }
        __syncthreads();   // exp(Ps), factors, V all visible

        // ---- prefetch next K chunk ----
        if (s0 + KT < S_) {
#pragma unroll
            for (int i = 0; i < 12; i++)
                rk[i] = *(const float4*)(qkv + ((size_t)b * S_ + s0 + KT + tok_[i]) * QKV_ + H_ + h * DH_ + dq_[i] * 4);
        }

        // ---- rescale + P @ V ----
        float f0 = fac_s[r0], f1 = fac_s[r0 + 8];
#pragma unroll
        for (int ni = 0; ni < 6; ni++) {
            Oacc[ni][0] *= f0; Oacc[ni][1] *= f0;
            Oacc[ni][2] *= f1; Oacc[ni][3] *= f1;
        }
#pragma unroll
        for (int ks = 0; ks < 8; ks++) {
            unsigned pa[4];
            int cb = ks * 8 + (lane & 3);
            pa[0] = __float_as_uint(Ps[r0 * PSP + cb]);
            pa[1] = __float_as_uint(Ps[(r0 + 8) * PSP + cb]);
            pa[2] = __float_as_uint(Ps[r0 * PSP + cb + 4]);
            pa[3] = __float_as_uint(Ps[(r0 + 8) * PSP + cb + 4]);
#pragma unroll
            for (int ni = 0; ni < 6; ni++) {
                uint2 vb = *(const uint2*)&KVs[((ks * 12 + warp_n * 6 + ni) * 32 + lane) * 2];
                mma_tf32(Oacc[ni], pa, (const unsigned*)&vb);
            }
        }
    }

    // ---- epilogue ----
    float inv0 = 1.0f / l_s[r0];
    float inv1 = 1.0f / l_s[r0 + 8];
#pragma unroll
    for (int ni = 0; ni < 6; ni++) {
        int col = h * DH_ + warp_n * 48 + ni * 8 + ((lane & 3) << 1);
        float2 lo = make_float2(Oacc[ni][0] * inv0, Oacc[ni][1] * inv0);
        float2 hi = make_float2(Oacc[ni][2] * inv1, Oacc[ni][3] * inv1);
        *(float2*)(out + ((size_t)b * LM_ + q0 + r0) * H_ + col)     = lo;
        *(float2*)(out + ((size_t)b * LM_ + q0 + r0 + 8) * H_ + col) = hi;
    }
}

// ---------------- masked mean-pool ----------------
__global__ __launch_bounds__(256) void pool_kernel(
    const float* __restrict__ hidden, const float* __restrict__ oproj,
    const int* __restrict__ line_starts, const int* __restrict__ line_lens,
    float* __restrict__ x)
{
    int bl = blockIdx.x;
    int b = bl / L_;
    int len = line_lens[bl];
    int start = line_starts[bl];
    float inv = 1.0f / (float)max(len, 1);
    for (int c = threadIdx.x; c < H_; c += 256) {
        float s1 = 0.0f, s2 = 0.0f;
        for (int m = 0; m < ML_; m++) {
            if (m < len) {
                int pos = min(max(start + m, 0), S_ - 1);
                s1 += hidden[((size_t)b * S_ + pos) * H_ + c];
                s2 += oproj[((size_t)bl * ML_ + m) * H_ + c];
            }
        }
        x[(size_t)bl * 2 * H_ + c]      = s1 * inv;
        x[(size_t)bl * 2 * H_ + H_ + c] = s2 * inv;
    }
}

// ---------------- LayerNorm -> exact GELU (+optional residual) ----------------
__global__ __launch_bounds__(256) void ln_gelu_kernel(
    const float* __restrict__ y, const float* __restrict__ g,
    const float* __restrict__ be, const float* __restrict__ res,
    float* __restrict__ out)
{
    __shared__ float red1[8], red2[8];
    int row = blockIdx.x;
    const float* yr = y + (size_t)row * H_;
    float v[3], sum = 0.0f, sq = 0.0f;
#pragma unroll
    for (int i = 0; i < 3; i++) {
        v[i] = yr[threadIdx.x + 256 * i];
        sum += v[i];
        sq  += v[i] * v[i];
    }
#pragma unroll
    for (int o = 16; o > 0; o >>= 1) {
        sum += __shfl_xor_sync(0xffffffffu, sum, o);
        sq  += __shfl_xor_sync(0xffffffffu, sq,  o);
    }
    int warp = threadIdx.x >> 5;
    if ((threadIdx.x & 31) == 0) { red1[warp] = sum; red2[warp] = sq; }
    __syncthreads();
    float tsum = 0.0f, tsq = 0.0f;
#pragma unroll
    for (int i = 0; i < 8; i++) { tsum += red1[i]; tsq += red2[i]; }
    float mean = tsum * (1.0f / H_);
    float var  = tsq  * (1.0f / H_) - mean * mean;
    float rstd = rsqrtf(var + 1e-5f);
#pragma unroll
    for (int i = 0; i < 3; i++) {
        int c = threadIdx.x + 256 * i;
        float t  = (v[i] - mean) * rstd * g[c] + be[c];
        float ge = 0.5f * t * (1.0f + erff(t * 0.70710678118654752f));
        out[(size_t)row * H_ + c] = (res ? res[(size_t)row * H_ + c] : 0.0f) + ge;
    }
}

// ---------------- final logit ----------------
__global__ __launch_bounds__(128) void final_kernel(
    const float* __restrict__ a2, const float* __restrict__ W3,
    const float* __restrict__ b3, const int* __restrict__ line_lens,
    float* __restrict__ out)
{
    int row  = blockIdx.x * 4 + (threadIdx.x >> 5);
    int lane = threadIdx.x & 31;
    float s = 0.0f;
    for (int c = lane; c < H_; c += 32)
        s += a2[(size_t)row * H_ + c] * W3[c];
#pragma unroll
    for (int o = 16; o > 0; o >>= 1) s += __shfl_xor_sync(0xffffffffu, s, o);
    if (lane == 0) {
        float logit = s + b3[0];
        if (line_lens[row] <= 0) logit = -10.0f;
        out[row] = 1.0f / (1.0f + __expf(-logit));
    }
}

// ---------------- launch ----------------
extern "C" void kernel_launch(void* const* d_in, const int* in_sizes, int n_in,
                              void* d_out, int out_size)
{
    (void)in_sizes; (void)n_in; (void)out_size;
    const float* hidden  = (const float*)d_in[0];
    const float* in_w    = (const float*)d_in[1];
    const float* in_b    = (const float*)d_in[2];
    const float* out_w   = (const float*)d_in[3];
    const float* out_b   = (const float*)d_in[4];
    const float* W1      = (const float*)d_in[5];
    const float* b1      = (const float*)d_in[6];
    const float* g1      = (const float*)d_in[7];
    const float* be1     = (const float*)d_in[8];
    const float* W2      = (const float*)d_in[9];
    const float* b2      = (const float*)d_in[10];
    const float* g2      = (const float*)d_in[11];
    const float* be2     = (const float*)d_in[12];
    const float* W3      = (const float*)d_in[13];
    const float* b3      = (const float*)d_in[14];
    const int*   lstarts = (const int*)d_in[15];
    const int*   llens   = (const int*)d_in[16];
    const int*   ctx     = (const int*)d_in[17];
    float* out = (float*)d_out;

    float *qkv, *attn, *oproj, *x, *y1, *y2;
    cudaGetSymbolAddress((void**)&qkv,   g_qkv);
    cudaGetSymbolAddress((void**)&attn,  g_attn);
    cudaGetSymbolAddress((void**)&oproj, g_oproj);
    cudaGetSymbolAddress((void**)&x,     g_x);
    cudaGetSymbolAddress((void**)&y1,    g_y1);
    cudaGetSymbolAddress((void**)&y2,    g_y2);

    // 1) QKV projection
    gemm_tf32_nt<<<dim3(QKV_ / 128, (B_ * S_) / 128), 256>>>(hidden, in_w, in_b, qkv,
                                                             B_ * S_, QKV_, H_);
    // 2) cross attention
    attn_kernel<<<dim3(LM_ / QT, NH_, B_), 128>>>(qkv, lstarts, ctx, attn);
    // 3) out_proj
    gemm_tf32_nt<<<dim3(H_ / 128, (B_ * LM_) / 128), 256>>>(attn, out_w, out_b, oproj,
                                                            B_ * LM_, H_, H_);
    // 4) pooled features
    pool_kernel<<<B_ * L_, 256>>>(hidden, oproj, lstarts, llens, x);
    // 5) classifier head
    gemm_tf32_nt<<<dim3(H_ / 128, (B_ * L_) / 128), 256>>>(x, W1, b1, y1, B_ * L_, H_, 2 * H_);
    ln_gelu_kernel<<<B_ * L_, 256>>>(y1, g1, be1, nullptr, y1);
    gemm_tf32_nt<<<dim3(H_ / 128, (B_ * L_) / 128), 256>>>(y1, W2, b2, y2, B_ * L_, H_, H_);
    ln_gelu_kernel<<<B_ * L_, 256>>>(y2, g2, be2, y1, y2);
    final_kernel<<<B_ * L_ / 4, 128>>>(y2, W3, b3, llens, out);
}

// round 5
// speedup vs baseline: 2.1102x; 2.1102x over previous
#include <cuda_runtime.h>
#include <math.h>
#include <stdint.h>

// ---------------- problem constants ----------------
#define B_    4
#define S_    2048
#define H_    768
#define NH_   8
#define DH_   96
#define L_    128
#define ML_   15
#define LM_   1920      // L_*ML_
#define QKV_  2304      // 3*H_

// ---------------- scratch ----------------
__device__ float g_qkv  [(size_t)B_ * S_  * QKV_];
__device__ float g_attn [(size_t)B_ * LM_ * H_];
__device__ float g_oproj[(size_t)B_ * LM_ * H_];
__device__ float g_x    [(size_t)B_ * L_ * 2 * H_];
__device__ float g_y1   [(size_t)B_ * L_ * H_];
__device__ float g_y2   [(size_t)B_ * L_ * H_];

// ---------------- tf32 mma (raw f32 bits; HW truncates to tf32) ----------------
__device__ __forceinline__ void mma_tf32(float* d, const unsigned* a, const unsigned* b) {
    asm volatile(
        "mma.sync.aligned.m16n8k8.row.col.f32.tf32.tf32.f32 "
        "{%0,%1,%2,%3}, {%4,%5,%6,%7}, {%8,%9}, {%0,%1,%2,%3};"
        : "+f"(d[0]), "+f"(d[1]), "+f"(d[2]), "+f"(d[3])
        : "r"(a[0]), "r"(a[1]), "r"(a[2]), "r"(a[3]), "r"(b[0]), "r"(b[1]));
}

// ---------------- tf32 NT GEMM (round-3 structure, no cvt) ----------------
// C[M,N] = A[M,K] @ B[N,K]^T + bias.  M%128==0, N%128==0, K%32==0.
__global__ __launch_bounds__(256) void gemm_tf32_nt(
    const float* __restrict__ A, const float* __restrict__ Bw,
    const float* __restrict__ bias, float* __restrict__ C,
    int M, int N, int K)
{
    __shared__ unsigned As[4 * 8 * 128];
    __shared__ unsigned Bs[4 * 16 * 64];

    int tid = threadIdx.x;
    int warp = tid >> 5, lane = tid & 31;
    int warp_m = warp >> 1, warp_n = warp & 1;
    int m0 = blockIdx.y * 128, n0 = blockIdx.x * 128;

    float acc[2][8][4];
#pragma unroll
    for (int mi = 0; mi < 2; mi++)
#pragma unroll
        for (int ni = 0; ni < 8; ni++)
#pragma unroll
            for (int r = 0; r < 4; r++) acc[mi][ni][r] = 0.0f;

    for (int k0 = 0; k0 < K; k0 += 32) {
        __syncthreads();
#pragma unroll
        for (int i = 0; i < 4; i++) {
            int f = tid + i * 256;
            int row = f >> 3, kq = f & 7;
            float4 v = *(const float4*)(A + (size_t)(m0 + row) * K + k0 + kq * 4);
            int mtile = row >> 4, r = row & 15, ktile = kq >> 1;
            int regb = (r >> 3) + ((kq & 1) << 1);
            unsigned* p = &As[((ktile * 8 + mtile) * 32 + (r & 7) * 4) * 4 + regb];
            p[0]  = __float_as_uint(v.x);
            p[4]  = __float_as_uint(v.y);
            p[8]  = __float_as_uint(v.z);
            p[12] = __float_as_uint(v.w);
        }
#pragma unroll
        for (int i = 0; i < 4; i++) {
            int f = tid + i * 256;
            int row = f >> 3, kq = f & 7;
            float4 v = *(const float4*)(Bw + (size_t)(n0 + row) * K + k0 + kq * 4);
            int ntile = row >> 3, ktile = kq >> 1, reg = kq & 1;
            unsigned* p = &Bs[(ktile * 16 + ntile) * 64 + (row & 7) * 8 + reg];
            p[0] = __float_as_uint(v.x);
            p[2] = __float_as_uint(v.y);
            p[4] = __float_as_uint(v.z);
            p[6] = __float_as_uint(v.w);
        }
        __syncthreads();
#pragma unroll
        for (int ks = 0; ks < 4; ks++) {
            uint4 a[2];
            uint2 b[8];
#pragma unroll
            for (int mi = 0; mi < 2; mi++)
                a[mi] = *(const uint4*)&As[((ks * 8 + warp_m * 2 + mi) * 32 + lane) * 4];
#pragma unroll
            for (int ni = 0; ni < 8; ni++)
                b[ni] = *(const uint2*)&Bs[((ks * 16 + warp_n * 8 + ni) * 32 + lane) * 2];
#pragma unroll
            for (int mi = 0; mi < 2; mi++)
#pragma unroll
                for (int ni = 0; ni < 8; ni++)
                    mma_tf32(acc[mi][ni], (const unsigned*)&a[mi], (const unsigned*)&b[ni]);
        }
    }

#pragma unroll
    for (int mi = 0; mi < 2; mi++) {
        int row = m0 + warp_m * 32 + mi * 16 + (lane >> 2);
#pragma unroll
        for (int ni = 0; ni < 8; ni++) {
            int col = n0 + warp_n * 64 + ni * 8 + ((lane & 3) << 1);
            float b0 = bias ? bias[col] : 0.0f;
            float b1 = bias ? bias[col + 1] : 0.0f;
            float2 lo = make_float2(acc[mi][ni][0] + b0, acc[mi][ni][1] + b1);
            float2 hi = make_float2(acc[mi][ni][2] + b0, acc[mi][ni][3] + b1);
            *(float2*)(C + (size_t)row * N + col)       = lo;
            *(float2*)(C + (size_t)(row + 8) * N + col) = hi;
        }
    }
}

// ---------------- tf32 flash cross-attention: QT=64, 8 warps ----------------
#define QT 64
#define KT 64
#define PSP 68
__global__ __launch_bounds__(256) void attn_kernel(
    const float* __restrict__ qkv,
    const int* __restrict__ line_starts,
    const int* __restrict__ ctx_len,
    float* __restrict__ out)
{
    __shared__ unsigned KVs[6144];               // 64 tok x 96 dims, frag-order
    __shared__ float Ps[QT * PSP];               // scores / probabilities
    __shared__ float m_s[QT], l_s[QT], fac_s[QT];

    int tid = threadIdx.x;
    int warp = tid >> 5, lane = tid & 31;
    int warp_m = warp >> 1;      // 0..3 : 16-query group
    int warp_n = warp & 1;       // 0..1 : token half (scores) / dim half (PV)
    int b = blockIdx.z, h = blockIdx.y, q0 = blockIdx.x * QT;
    const float scale = 0.10206207261596577f;    // 1/sqrt(96)

    // ---- prologue: load Q fragments straight from gmem ----
    // a-frag mapping (m16n8k8): a0=(r0,c), a1=(r0+8,c), a2=(r0,c+4), a3=(r0+8,c+4)
    int r0 = warp_m * 16 + (lane >> 2);
    int kc = lane & 3;
    const float *qp0, *qp1;
    {
        int gq0 = q0 + r0;
        int l0 = gq0 / ML_, mm0 = gq0 - l0 * ML_;
        int pos0 = min(max(line_starts[b * L_ + l0] + mm0, 0), S_ - 1);
        int gq1 = gq0 + 8;
        int l1 = gq1 / ML_, mm1 = gq1 - l1 * ML_;
        int pos1 = min(max(line_starts[b * L_ + l1] + mm1, 0), S_ - 1);
        qp0 = qkv + ((size_t)b * S_ + pos0) * QKV_ + h * DH_;
        qp1 = qkv + ((size_t)b * S_ + pos1) * QKV_ + h * DH_;
    }
    uint4 qf[12];
#pragma unroll
    for (int ks = 0; ks < 12; ks++) {
        int col = ks * 8 + kc;
        qf[ks].x = __float_as_uint(qp0[col]     * scale);
        qf[ks].y = __float_as_uint(qp1[col]     * scale);
        qf[ks].z = __float_as_uint(qp0[col + 4] * scale);
        qf[ks].w = __float_as_uint(qp1[col + 4] * scale);
    }
    if (tid < QT) { m_s[tid] = -3e38f; l_s[tid] = 0.0f; }
    int ctx = ctx_len[b];

    float Oacc[6][4];
#pragma unroll
    for (int ni = 0; ni < 6; ni++)
#pragma unroll
        for (int r = 0; r < 4; r++) Oacc[ni][r] = 0.0f;

    __syncthreads();

    for (int s0 = 0; s0 < S_; s0 += KT) {
        // ---- K chunk -> fragment-order smem (B-matrix: n=token, k=dim) ----
#pragma unroll
        for (int i = 0; i < 6; i++) {
            int f = tid + i * 256;          // 1536 float4s = 64 tok * 24
            int token = f / 24, dq = f - token * 24;
            float4 v = *(const float4*)(qkv + ((size_t)b * S_ + s0 + token) * QKV_ + H_ + h * DH_ + dq * 4);
            int ktile = dq >> 1, ntile = token >> 3, reg = dq & 1;
            unsigned* p = &KVs[(ktile * 8 + ntile) * 64 + (token & 7) * 8 + reg];
            p[0] = __float_as_uint(v.x);
            p[2] = __float_as_uint(v.y);
            p[4] = __float_as_uint(v.z);
            p[6] = __float_as_uint(v.w);
        }
        __syncthreads();

        // ---- scores: each warp 16q x 32tok ----
        float sacc[4][4];
#pragma unroll
        for (int ni = 0; ni < 4; ni++)
#pragma unroll
            for (int r = 0; r < 4; r++) sacc[ni][r] = 0.0f;
#pragma unroll
        for (int ks = 0; ks < 12; ks++) {
            uint2 kb[4];
#pragma unroll
            for (int ni = 0; ni < 4; ni++)
                kb[ni] = *(const uint2*)&KVs[((ks * 8 + warp_n * 4 + ni) * 32 + lane) * 2];
#pragma unroll
            for (int ni = 0; ni < 4; ni++)
                mma_tf32(sacc[ni], (const unsigned*)&qf[ks], (const unsigned*)&kb[ni]);
        }
#pragma unroll
        for (int ni = 0; ni < 4; ni++) {
            int cb = warp_n * 32 + ni * 8 + ((lane & 3) << 1);
            int s_g = s0 + cb;
            Ps[r0 * PSP + cb]           = (s_g     < ctx) ? sacc[ni][0] : -1e9f;
            Ps[r0 * PSP + cb + 1]       = (s_g + 1 < ctx) ? sacc[ni][1] : -1e9f;
            Ps[(r0 + 8) * PSP + cb]     = (s_g     < ctx) ? sacc[ni][2] : -1e9f;
            Ps[(r0 + 8) * PSP + cb + 1] = (s_g + 1 < ctx) ? sacc[ni][3] : -1e9f;
        }
        __syncthreads();   // Ps complete; all K-region reads done

        // ---- online softmax: one quad per query row (256 thr = 64 rows) ----
        {
            int row = tid >> 2, sub = tid & 3;
            float mx = -3e38f;
#pragma unroll
            for (int k = sub; k < KT; k += 4) mx = fmaxf(mx, Ps[row * PSP + k]);
            mx = fmaxf(mx, __shfl_xor_sync(0xffffffffu, mx, 1));
            mx = fmaxf(mx, __shfl_xor_sync(0xffffffffu, mx, 2));
            float mold = m_s[row];
            float mnew = fmaxf(mold, mx);
            float lsum = 0.0f;
#pragma unroll
            for (int k = sub; k < KT; k += 4) {
                float p = __expf(Ps[row * PSP + k] - mnew);
                Ps[row * PSP + k] = p;
                lsum += p;
            }
            lsum += __shfl_xor_sync(0xffffffffu, lsum, 1);
            lsum += __shfl_xor_sync(0xffffffffu, lsum, 2);
            if (sub == 0) {
                float fct = __expf(mold - mnew);
                m_s[row]   = mnew;
                l_s[row]   = l_s[row] * fct + lsum;
                fac_s[row] = fct;
            }
        }
        // ---- V chunk -> fragment-order (B-matrix: k=token, n=dim) ----
#pragma unroll
        for (int i = 0; i < 6; i++) {
            int f = tid + i * 256;
            int token = f / 24, dq = f - token * 24;
            int d0 = dq * 4;
            float4 v = *(const float4*)(qkv + ((size_t)b * S_ + s0 + token) * QKV_ + 2 * H_ + h * DH_ + d0);
            int ktile = token >> 3, ntile = dq >> 1;
            int reg = (token & 4) >> 2;
            int laneb = (d0 & 7) * 4 + (token & 3);
            unsigned* p = &KVs[(ktile * 12 + ntile) * 64 + laneb * 2 + reg];
            p[0]  = __float_as_uint(v.x);
            p[8]  = __float_as_uint(v.y);
            p[16] = __float_as_uint(v.z);
            p[24] = __float_as_uint(v.w);
        }
        __syncthreads();   // exp(Ps), factors, V all visible

        // ---- rescale + P @ V (each warp 16q x 48d) ----
        float f0 = fac_s[r0], f1 = fac_s[r0 + 8];
#pragma unroll
        for (int ni = 0; ni < 6; ni++) {
            Oacc[ni][0] *= f0; Oacc[ni][1] *= f0;
            Oacc[ni][2] *= f1; Oacc[ni][3] *= f1;
        }
#pragma unroll
        for (int ks = 0; ks < 8; ks++) {
            unsigned pa[4];
            int cb = ks * 8 + (lane & 3);
            pa[0] = __float_as_uint(Ps[r0 * PSP + cb]);
            pa[1] = __float_as_uint(Ps[(r0 + 8) * PSP + cb]);
            pa[2] = __float_as_uint(Ps[r0 * PSP + cb + 4]);
            pa[3] = __float_as_uint(Ps[(r0 + 8) * PSP + cb + 4]);
#pragma unroll
            for (int ni = 0; ni < 6; ni++) {
                uint2 vb = *(const uint2*)&KVs[((ks * 12 + warp_n * 6 + ni) * 32 + lane) * 2];
                mma_tf32(Oacc[ni], pa, (const unsigned*)&vb);
            }
        }
        __syncthreads();   // PV reads done before next chunk overwrites KVs/Ps
    }

    // ---- epilogue ----
    float inv0 = 1.0f / l_s[r0];
    float inv1 = 1.0f / l_s[r0 + 8];
#pragma unroll
    for (int ni = 0; ni < 6; ni++) {
        int col = h * DH_ + warp_n * 48 + ni * 8 + ((lane & 3) << 1);
        float2 lo = make_float2(Oacc[ni][0] * inv0, Oacc[ni][1] * inv0);
        float2 hi = make_float2(Oacc[ni][2] * inv1, Oacc[ni][3] * inv1);
        *(float2*)(out + ((size_t)b * LM_ + q0 + r0) * H_ + col)     = lo;
        *(float2*)(out + ((size_t)b * LM_ + q0 + r0 + 8) * H_ + col) = hi;
    }
}

// ---------------- masked mean-pool ----------------
__global__ __launch_bounds__(256) void pool_kernel(
    const float* __restrict__ hidden, const float* __restrict__ oproj,
    const int* __restrict__ line_starts, const int* __restrict__ line_lens,
    float* __restrict__ x)
{
    int bl = blockIdx.x;
    int b = bl / L_;
    int len = line_lens[bl];
    int start = line_starts[bl];
    float inv = 1.0f / (float)max(len, 1);
    for (int c = threadIdx.x; c < H_; c += 256) {
        float s1 = 0.0f, s2 = 0.0f;
        for (int m = 0; m < ML_; m++) {
            if (m < len) {
                int pos = min(max(start + m, 0), S_ - 1);
                s1 += hidden[((size_t)b * S_ + pos) * H_ + c];
                s2 += oproj[((size_t)bl * ML_ + m) * H_ + c];
            }
        }
        x[(size_t)bl * 2 * H_ + c]      = s1 * inv;
        x[(size_t)bl * 2 * H_ + H_ + c] = s2 * inv;
    }
}

// ---------------- LayerNorm -> exact GELU (+optional residual) ----------------
__global__ __launch_bounds__(256) void ln_gelu_kernel(
    const float* __restrict__ y, const float* __restrict__ g,
    const float* __restrict__ be, const float* __restrict__ res,
    float* __restrict__ out)
{
    __shared__ float red1[8], red2[8];
    int row = blockIdx.x;
    const float* yr = y + (size_t)row * H_;
    float v[3], sum = 0.0f, sq = 0.0f;
#pragma unroll
    for (int i = 0; i < 3; i++) {
        v[i] = yr[threadIdx.x + 256 * i];
        sum += v[i];
        sq  += v[i] * v[i];
    }
#pragma unroll
    for (int o = 16; o > 0; o >>= 1) {
        sum += __shfl_xor_sync(0xffffffffu, sum, o);
        sq  += __shfl_xor_sync(0xffffffffu, sq,  o);
    }
    int warp = threadIdx.x >> 5;
    if ((threadIdx.x & 31) == 0) { red1[warp] = sum; red2[warp] = sq; }
    __syncthreads();
    float tsum = 0.0f, tsq = 0.0f;
#pragma unroll
    for (int i = 0; i < 8; i++) { tsum += red1[i]; tsq += red2[i]; }
    float mean = tsum * (1.0f / H_);
    float var  = tsq  * (1.0f / H_) - mean * mean;
    float rstd = rsqrtf(var + 1e-5f);
#pragma unroll
    for (int i = 0; i < 3; i++) {
        int c = threadIdx.x + 256 * i;
        float t  = (v[i] - mean) * rstd * g[c] + be[c];
        float ge = 0.5f * t * (1.0f + erff(t * 0.70710678118654752f));
        out[(size_t)row * H_ + c] = (res ? res[(size_t)row * H_ + c] : 0.0f) + ge;
    }
}

// ---------------- final logit ----------------
__global__ __launch_bounds__(128) void final_kernel(
    const float* __restrict__ a2, const float* __restrict__ W3,
    const float* __restrict__ b3, const int* __restrict__ line_lens,
    float* __restrict__ out)
{
    int row  = blockIdx.x * 4 + (threadIdx.x >> 5);
    int lane = threadIdx.x & 31;
    float s = 0.0f;
    for (int c = lane; c < H_; c += 32)
        s += a2[(size_t)row * H_ + c] * W3[c];
#pragma unroll
    for (int o = 16; o > 0; o >>= 1) s += __shfl_xor_sync(0xffffffffu, s, o);
    if (lane == 0) {
        float logit = s + b3[0];
        if (line_lens[row] <= 0) logit = -10.0f;
        out[row] = 1.0f / (1.0f + __expf(-logit));
    }
}

// ---------------- launch ----------------
extern "C" void kernel_launch(void* const* d_in, const int* in_sizes, int n_in,
                              void* d_out, int out_size)
{
    (void)in_sizes; (void)n_in; (void)out_size;
    const float* hidden  = (const float*)d_in[0];
    const float* in_w    = (const float*)d_in[1];
    const float* in_b    = (const float*)d_in[2];
    const float* out_w   = (const float*)d_in[3];
    const float* out_b   = (const float*)d_in[4];
    const float* W1      = (const float*)d_in[5];
    const float* b1      = (const float*)d_in[6];
    const float* g1      = (const float*)d_in[7];
    const float* be1     = (const float*)d_in[8];
    const float* W2      = (const float*)d_in[9];
    const float* b2      = (const float*)d_in[10];
    const float* g2      = (const float*)d_in[11];
    const float* be2     = (const float*)d_in[12];
    const float* W3      = (const float*)d_in[13];
    const float* b3      = (const float*)d_in[14];
    const int*   lstarts = (const int*)d_in[15];
    const int*   llens   = (const int*)d_in[16];
    const int*   ctx     = (const int*)d_in[17];
    float* out = (float*)d_out;

    float *qkv, *attn, *oproj, *x, *y1, *y2;
    cudaGetSymbolAddress((void**)&qkv,   g_qkv);
    cudaGetSymbolAddress((void**)&attn,  g_attn);
    cudaGetSymbolAddress((void**)&oproj, g_oproj);
    cudaGetSymbolAddress((void**)&x,     g_x);
    cudaGetSymbolAddress((void**)&y1,    g_y1);
    cudaGetSymbolAddress((void**)&y2,    g_y2);

    // 1) QKV projection
    gemm_tf32_nt<<<dim3(QKV_ / 128, (B_ * S_) / 128), 256>>>(hidden, in_w, in_b, qkv,
                                                             B_ * S_, QKV_, H_);
    // 2) cross attention (64 queries per CTA)
    attn_kernel<<<dim3(LM_ / QT, NH_, B_), 256>>>(qkv, lstarts, ctx, attn);
    // 3) out_proj
    gemm_tf32_nt<<<dim3(H_ / 128, (B_ * LM_) / 128), 256>>>(attn, out_w, out_b, oproj,
                                                            B_ * LM_, H_, H_);
    // 4) pooled features
    pool_kernel<<<B_ * L_, 256>>>(hidden, oproj, lstarts, llens, x);
    // 5) classifier head
    gemm_tf32_nt<<<dim3(H_ / 128, (B_ * L_) / 128), 256>>>(x, W1, b1, y1, B_ * L_, H_, 2 * H_);
    ln_gelu_kernel<<<B_ * L_, 256>>>(y1, g1, be1, nullptr, y1);
    gemm_tf32_nt<<<dim3(H_ / 128, (B_ * L_) / 128), 256>>>(y1, W2, b2, y2, B_ * L_, H_, H_);
    ln_gelu_kernel<<<B_ * L_, 256>>>(y2, g2, be2, y1, y2);
    final_kernel<<<B_ * L_ / 4, 128>>>(y2, W3, b3, llens, out);
}

// round 7
// speedup vs baseline: 4.3020x; 2.0387x over previous
#include <cuda_runtime.h>
#include <math.h>
#include <stdint.h>

// ---------------- problem constants ----------------
#define B_    4
#define S_    2048
#define H_    768
#define NH_   8
#define DH_   96
#define L_    128
#define ML_   15
#define LM_   1920      // L_*ML_
#define QKV_  2304      // 3*H_

// ---------------- scratch ----------------
__device__ float g_qkv  [(size_t)B_ * S_  * QKV_];
__device__ float g_attn [(size_t)B_ * LM_ * H_];
__device__ float g_oproj[(size_t)B_ * LM_ * H_];
__device__ float g_x    [(size_t)B_ * L_ * 2 * H_];
__device__ float g_y1   [(size_t)B_ * L_ * H_];
__device__ float g_y2   [(size_t)B_ * L_ * H_];

// ---------------- helpers ----------------
__device__ __forceinline__ unsigned pk(float lo, float hi) {
    unsigned r;
    asm("cvt.rn.bf16x2.f32 %0, %1, %2;" : "=r"(r) : "f"(hi), "f"(lo));
    return r;
}
__device__ __forceinline__ float ex2(float x) {
    float r;
    asm("ex2.approx.ftz.f32 %0, %1;" : "=f"(r) : "f"(x));
    return r;
}
__device__ __forceinline__ void mma_bf16(float* d, const unsigned* a, const unsigned* b) {
    asm volatile(
        "mma.sync.aligned.m16n8k16.row.col.f32.bf16.bf16.f32 "
        "{%0,%1,%2,%3}, {%4,%5,%6,%7}, {%8,%9}, {%0,%1,%2,%3};"
        : "+f"(d[0]), "+f"(d[1]), "+f"(d[2]), "+f"(d[3])
        : "r"(a[0]), "r"(a[1]), "r"(a[2]), "r"(a[3]), "r"(b[0]), "r"(b[1]));
}
__device__ __forceinline__ void mma_tf32(float* d, const unsigned* a, const unsigned* b) {
    asm volatile(
        "mma.sync.aligned.m16n8k8.row.col.f32.tf32.tf32.f32 "
        "{%0,%1,%2,%3}, {%4,%5,%6,%7}, {%8,%9}, {%0,%1,%2,%3};"
        : "+f"(d[0]), "+f"(d[1]), "+f"(d[2]), "+f"(d[3])
        : "r"(a[0]), "r"(a[1]), "r"(a[2]), "r"(a[3]), "r"(b[0]), "r"(b[1]));
}

// ---------------- bf16 NT GEMM: C[M,N] = A[M,K] @ B[N,K]^T + bias ----------------
// M%128==0, N%128==0, K%64==0. 256 thr, tile 128x128x64.
__global__ __launch_bounds__(256) void gemm_bf16_nt(
    const float* __restrict__ A, const float* __restrict__ Bw,
    const float* __restrict__ bias, float* __restrict__ C,
    int M, int N, int K)
{
    __shared__ unsigned As[4 * 8 * 128];   // [k16tile][mtile][lane*4+reg]
    __shared__ unsigned Bs[4 * 16 * 64];   // [k16tile][ntile][lane*2+reg]

    int tid = threadIdx.x;
    int warp = tid >> 5, lane = tid & 31;
    int warp_m = warp >> 1, warp_n = warp & 1;
    int m0 = blockIdx.y * 128, n0 = blockIdx.x * 128;

    float acc[2][8][4];
#pragma unroll
    for (int mi = 0; mi < 2; mi++)
#pragma unroll
        for (int ni = 0; ni < 8; ni++)
#pragma unroll
            for (int r = 0; r < 4; r++) acc[mi][ni][r] = 0.0f;

    for (int k0 = 0; k0 < K; k0 += 64) {
        __syncthreads();
        // ---- A fill: 128 rows x 64 k ----
#pragma unroll
        for (int i = 0; i < 8; i++) {
            int u = tid + i * 256;
            int row = u >> 4, kq = u & 15;
            float4 v = *(const float4*)(A + (size_t)(m0 + row) * K + k0 + kq * 4);
            int kt = kq >> 2, pp = 2 * (kq & 3);
            int mt = row >> 4, rq = row & 15;
            int base = ((kt * 8 + mt) * 32 + (rq & 7) * 4);
            int reg0 = (rq >> 3) + 2 * (pp >> 2);
            As[(base + (pp & 3)) * 4 + reg0]       = pk(v.x, v.y);
            As[(base + ((pp + 1) & 3)) * 4 + reg0] = pk(v.z, v.w);
        }
        // ---- B fill ----
#pragma unroll
        for (int i = 0; i < 8; i++) {
            int u = tid + i * 256;
            int row = u >> 4, kq = u & 15;
            float4 v = *(const float4*)(Bw + (size_t)(n0 + row) * K + k0 + kq * 4);
            int kt = kq >> 2, pp = 2 * (kq & 3);
            int nt = row >> 3;
            int base = ((kt * 16 + nt) * 32 + (row & 7) * 4);
            int h2 = pp >> 2;
            Bs[(base + (pp & 3)) * 2 + h2]       = pk(v.x, v.y);
            Bs[(base + ((pp + 1) & 3)) * 2 + h2] = pk(v.z, v.w);
        }
        __syncthreads();
        // ---- compute: 4 k16-steps ----
#pragma unroll
        for (int ks = 0; ks < 4; ks++) {
            uint4 a[2];
            uint2 b[8];
#pragma unroll
            for (int mi = 0; mi < 2; mi++)
                a[mi] = *(const uint4*)&As[((ks * 8 + warp_m * 2 + mi) * 32 + lane) * 4];
#pragma unroll
            for (int ni = 0; ni < 8; ni++)
                b[ni] = *(const uint2*)&Bs[((ks * 16 + warp_n * 8 + ni) * 32 + lane) * 2];
#pragma unroll
            for (int mi = 0; mi < 2; mi++)
#pragma unroll
                for (int ni = 0; ni < 8; ni++)
                    mma_bf16(acc[mi][ni], (const unsigned*)&a[mi], (const unsigned*)&b[ni]);
        }
    }

#pragma unroll
    for (int mi = 0; mi < 2; mi++) {
        int row = m0 + warp_m * 32 + mi * 16 + (lane >> 2);
#pragma unroll
        for (int ni = 0; ni < 8; ni++) {
            int col = n0 + warp_n * 64 + ni * 8 + ((lane & 3) << 1);
            float b0 = bias ? bias[col] : 0.0f;
            float b1 = bias ? bias[col + 1] : 0.0f;
            float2 lo = make_float2(acc[mi][ni][0] + b0, acc[mi][ni][1] + b1);
            float2 hi = make_float2(acc[mi][ni][2] + b0, acc[mi][ni][3] + b1);
            *(float2*)(C + (size_t)row * N + col)       = lo;
            *(float2*)(C + (size_t)(row + 8) * N + col) = hi;
        }
    }
}

// ---------------- tf32 NT GEMM (classifier; round-3 structure) ----------------
__global__ __launch_bounds__(256) void gemm_tf32_nt(
    const float* __restrict__ A, const float* __restrict__ Bw,
    const float* __restrict__ bias, float* __restrict__ C,
    int M, int N, int K)
{
    __shared__ unsigned As[4 * 8 * 128];
    __shared__ unsigned Bs[4 * 16 * 64];

    int tid = threadIdx.x;
    int warp = tid >> 5, lane = tid & 31;
    int warp_m = warp >> 1, warp_n = warp & 1;
    int m0 = blockIdx.y * 128, n0 = blockIdx.x * 128;

    float acc[2][8][4];
#pragma unroll
    for (int mi = 0; mi < 2; mi++)
#pragma unroll
        for (int ni = 0; ni < 8; ni++)
#pragma unroll
            for (int r = 0; r < 4; r++) acc[mi][ni][r] = 0.0f;

    for (int k0 = 0; k0 < K; k0 += 32) {
        __syncthreads();
#pragma unroll
        for (int i = 0; i < 4; i++) {
            int f = tid + i * 256;
            int row = f >> 3, kq = f & 7;
            float4 v = *(const float4*)(A + (size_t)(m0 + row) * K + k0 + kq * 4);
            int mtile = row >> 4, r = row & 15, ktile = kq >> 1;
            int regb = (r >> 3) + ((kq & 1) << 1);
            unsigned* p = &As[((ktile * 8 + mtile) * 32 + (r & 7) * 4) * 4 + regb];
            p[0]  = __float_as_uint(v.x);
            p[4]  = __float_as_uint(v.y);
            p[8]  = __float_as_uint(v.z);
            p[12] = __float_as_uint(v.w);
        }
#pragma unroll
        for (int i = 0; i < 4; i++) {
            int f = tid + i * 256;
            int row = f >> 3, kq = f & 7;
            float4 v = *(const float4*)(Bw + (size_t)(n0 + row) * K + k0 + kq * 4);
            int ntile = row >> 3, ktile = kq >> 1, reg = kq & 1;
            unsigned* p = &Bs[(ktile * 16 + ntile) * 64 + (row & 7) * 8 + reg];
            p[0] = __float_as_uint(v.x);
            p[2] = __float_as_uint(v.y);
            p[4] = __float_as_uint(v.z);
            p[6] = __float_as_uint(v.w);
        }
        __syncthreads();
#pragma unroll
        for (int ks = 0; ks < 4; ks++) {
            uint4 a[2];
            uint2 b[8];
#pragma unroll
            for (int mi = 0; mi < 2; mi++)
                a[mi] = *(const uint4*)&As[((ks * 8 + warp_m * 2 + mi) * 32 + lane) * 4];
#pragma unroll
            for (int ni = 0; ni < 8; ni++)
                b[ni] = *(const uint2*)&Bs[((ks * 16 + warp_n * 8 + ni) * 32 + lane) * 2];
#pragma unroll
            for (int mi = 0; mi < 2; mi++)
#pragma unroll
                for (int ni = 0; ni < 8; ni++)
                    mma_tf32(acc[mi][ni], (const unsigned*)&a[mi], (const unsigned*)&b[ni]);
        }
    }

#pragma unroll
    for (int mi = 0; mi < 2; mi++) {
        int row = m0 + warp_m * 32 + mi * 16 + (lane >> 2);
#pragma unroll
        for (int ni = 0; ni < 8; ni++) {
            int col = n0 + warp_n * 64 + ni * 8 + ((lane & 3) << 1);
            float b0 = bias ? bias[col] : 0.0f;
            float b1 = bias ? bias[col + 1] : 0.0f;
            float2 lo = make_float2(acc[mi][ni][0] + b0, acc[mi][ni][1] + b1);
            float2 hi = make_float2(acc[mi][ni][2] + b0, acc[mi][ni][3] + b1);
            *(float2*)(C + (size_t)row * N + col)       = lo;
            *(float2*)(C + (size_t)(row + 8) * N + col) = hi;
        }
    }
}

// ---------------- bf16 flash cross-attention: QT=128, register softmax ----------------
// grid: (LM/128, NH, B); 256 threads (8 warps, 16 queries each).
__global__ __launch_bounds__(256) void attn_kernel(
    const float* __restrict__ qkv,
    const int* __restrict__ line_starts,
    const int* __restrict__ ctx_len,
    float* __restrict__ out)
{
    __shared__ unsigned Ks[6 * 8 * 64];   // K tile: [d16tile][tok8tile][lane*2+reg] (12KB)
    __shared__ unsigned Vs[4 * 12 * 64];  // V tile: [tok16tile][d8tile][lane*2+reg] (12KB)

    int tid = threadIdx.x;
    int warp = tid >> 5, lane = tid & 31;
    int b = blockIdx.z, h = blockIdx.y, q0 = blockIdx.x * 128;
    // scale * log2(e): scores land in log2 domain -> single-MUFU exp
    const float qscale = 0.10206207261596577f * 1.4426950408889634f;

    int r0 = warp * 16 + (lane >> 2);
    int c2 = (lane & 3) * 2;
    int ctx = ctx_len[b];

    // ---- Q fragments straight from gmem (gathered line tokens) ----
    const float *qp0, *qp1;
    {
        int gq0 = q0 + r0;
        int l0i = gq0 / ML_, mm0 = gq0 - l0i * ML_;
        int pos0 = min(max(line_starts[b * L_ + l0i] + mm0, 0), S_ - 1);
        int gq1 = gq0 + 8;
        int l1i = gq1 / ML_, mm1 = gq1 - l1i * ML_;
        int pos1 = min(max(line_starts[b * L_ + l1i] + mm1, 0), S_ - 1);
        qp0 = qkv + ((size_t)b * S_ + pos0) * QKV_ + h * DH_;
        qp1 = qkv + ((size_t)b * S_ + pos1) * QKV_ + h * DH_;
    }
    unsigned qf[6][4];
#pragma unroll
    for (int ks = 0; ks < 6; ks++) {
        float2 u0 = *(const float2*)(qp0 + ks * 16 + c2);
        float2 u1 = *(const float2*)(qp1 + ks * 16 + c2);
        float2 w0 = *(const float2*)(qp0 + ks * 16 + c2 + 8);
        float2 w1 = *(const float2*)(qp1 + ks * 16 + c2 + 8);
        qf[ks][0] = pk(u0.x * qscale, u0.y * qscale);
        qf[ks][1] = pk(u1.x * qscale, u1.y * qscale);
        qf[ks][2] = pk(w0.x * qscale, w0.y * qscale);
        qf[ks][3] = pk(w1.x * qscale, w1.y * qscale);
    }

    float m0 = -1e30f, m1 = -1e30f, l0 = 0.0f, l1 = 0.0f;
    float Oacc[12][4];
#pragma unroll
    for (int nt = 0; nt < 12; nt++)
#pragma unroll
        for (int r = 0; r < 4; r++) Oacc[nt][r] = 0.0f;

    for (int s0 = 0; s0 < S_; s0 += 64) {
        // ---- K fill: 64 tok x 96 d -> bf16 frag-order ----
#pragma unroll
        for (int i = 0; i < 6; i++) {
            int u = tid + i * 256;
            int tok = u / 24, dq = u - tok * 24;
            float4 v = *(const float4*)(qkv + ((size_t)b * S_ + s0 + tok) * QKV_ + H_ + h * DH_ + dq * 4);
            int kt = dq >> 2, pp = 2 * (dq & 3);
            int base = ((kt * 8 + (tok >> 3)) * 32 + (tok & 7) * 4);
            int h2 = pp >> 2;
            Ks[(base + (pp & 3)) * 2 + h2]       = pk(v.x, v.y);
            Ks[(base + ((pp + 1) & 3)) * 2 + h2] = pk(v.z, v.w);
        }
        // ---- V fill: pairs span 2 consecutive tokens (k-dim) ----
#pragma unroll
        for (int i = 0; i < 6; i++) {
            int u = tid + i * 256;
            int j = u % 48, r = u / 48;
            int pq = r & 7, tt = r >> 3;
            int t0 = s0 + tt * 16 + pq * 2;
            const float* vptr = qkv + ((size_t)b * S_ + t0) * QKV_ + 2 * H_ + h * DH_ + 2 * j;
            float2 va = *(const float2*)(vptr);
            float2 vb = *(const float2*)(vptr + QKV_);
            int d0 = 2 * j, c = pq & 3, rg = pq >> 2;
            Vs[((tt * 12 + (d0 >> 3)) * 32 + (d0 & 7) * 4 + c) * 2 + rg] = pk(va.x, vb.x);
            int d1 = d0 + 1;
            Vs[((tt * 12 + (d1 >> 3)) * 32 + (d1 & 7) * 4 + c) * 2 + rg] = pk(va.y, vb.y);
        }
        __syncthreads();

        // ---- scores: 16q x 64tok per warp ----
        float sacc[8][4];
#pragma unroll
        for (int nt = 0; nt < 8; nt++)
#pragma unroll
            for (int r = 0; r < 4; r++) sacc[nt][r] = 0.0f;
#pragma unroll
        for (int ks = 0; ks < 6; ks++) {
#pragma unroll
            for (int nt = 0; nt < 8; nt++) {
                uint2 kb = *(const uint2*)&Ks[((ks * 8 + nt) * 32 + lane) * 2];
                mma_bf16(sacc[nt], qf[ks], (const unsigned*)&kb);
            }
        }

        // ---- register softmax (online) ----
        float mx0 = -1e30f, mx1 = -1e30f;
#pragma unroll
        for (int nt = 0; nt < 8; nt++) {
            int t = s0 + nt * 8 + c2;
            if (t >= ctx)     { sacc[nt][0] = -1e30f; sacc[nt][2] = -1e30f; }
            if (t + 1 >= ctx) { sacc[nt][1] = -1e30f; sacc[nt][3] = -1e30f; }
            mx0 = fmaxf(mx0, fmaxf(sacc[nt][0], sacc[nt][1]));
            mx1 = fmaxf(mx1, fmaxf(sacc[nt][2], sacc[nt][3]));
        }
        mx0 = fmaxf(mx0, __shfl_xor_sync(0xffffffffu, mx0, 1));
        mx0 = fmaxf(mx0, __shfl_xor_sync(0xffffffffu, mx0, 2));
        mx1 = fmaxf(mx1, __shfl_xor_sync(0xffffffffu, mx1, 1));
        mx1 = fmaxf(mx1, __shfl_xor_sync(0xffffffffu, mx1, 2));
        float mn0 = fmaxf(m0, mx0), mn1 = fmaxf(m1, mx1);
        float fac0 = ex2(m0 - mn0), fac1 = ex2(m1 - mn1);
        float sum0 = 0.0f, sum1 = 0.0f;
#pragma unroll
        for (int nt = 0; nt < 8; nt++) {
            int t = s0 + nt * 8 + c2;
            float p0 = (t < ctx)     ? ex2(sacc[nt][0] - mn0) : 0.0f;
            float p1 = (t + 1 < ctx) ? ex2(sacc[nt][1] - mn0) : 0.0f;
            float p2 = (t < ctx)     ? ex2(sacc[nt][2] - mn1) : 0.0f;
            float p3 = (t + 1 < ctx) ? ex2(sacc[nt][3] - mn1) : 0.0f;
            sacc[nt][0] = p0; sacc[nt][1] = p1; sacc[nt][2] = p2; sacc[nt][3] = p3;
            sum0 += p0 + p1;
            sum1 += p2 + p3;
        }
        sum0 += __shfl_xor_sync(0xffffffffu, sum0, 1);
        sum0 += __shfl_xor_sync(0xffffffffu, sum0, 2);
        sum1 += __shfl_xor_sync(0xffffffffu, sum1, 1);
        sum1 += __shfl_xor_sync(0xffffffffu, sum1, 2);
        l0 = l0 * fac0 + sum0;  m0 = mn0;
        l1 = l1 * fac1 + sum1;  m1 = mn1;

        // ---- rescale + P@V: acc pairs ARE the a-frags (in-thread repack) ----
#pragma unroll
        for (int nt = 0; nt < 12; nt++) {
            Oacc[nt][0] *= fac0; Oacc[nt][1] *= fac0;
            Oacc[nt][2] *= fac1; Oacc[nt][3] *= fac1;
        }
#pragma unroll
        for (int ks = 0; ks < 4; ks++) {
            unsigned pa[4];
            pa[0] = pk(sacc[2 * ks][0],     sacc[2 * ks][1]);
            pa[1] = pk(sacc[2 * ks][2],     sacc[2 * ks][3]);
            pa[2] = pk(sacc[2 * ks + 1][0], sacc[2 * ks + 1][1]);
            pa[3] = pk(sacc[2 * ks + 1][2], sacc[2 * ks + 1][3]);
#pragma unroll
            for (int nt = 0; nt < 12; nt++) {
                uint2 vb2 = *(const uint2*)&Vs[((ks * 12 + nt) * 32 + lane) * 2];
                mma_bf16(Oacc[nt], pa, (const unsigned*)&vb2);
            }
        }
        __syncthreads();   // PV reads done before next chunk overwrites Ks/Vs
    }

    // ---- epilogue ----
    float inv0 = 1.0f / l0;
    float inv1 = 1.0f / l1;
#pragma unroll
    for (int nt = 0; nt < 12; nt++) {
        int col = h * DH_ + nt * 8 + c2;
        float2 lo = make_float2(Oacc[nt][0] * inv0, Oacc[nt][1] * inv0);
        float2 hi = make_float2(Oacc[nt][2] * inv1, Oacc[nt][3] * inv1);
        *(float2*)(out + ((size_t)b * LM_ + q0 + r0) * H_ + col)     = lo;
        *(float2*)(out + ((size_t)b * LM_ + q0 + r0 + 8) * H_ + col) = hi;
    }
}

// ---------------- masked mean-pool ----------------
__global__ __launch_bounds__(256) void pool_kernel(
    const float* __restrict__ hidden, const float* __restrict__ oproj,
    const int* __restrict__ line_starts, const int* __restrict__ line_lens,
    float* __restrict__ x)
{
    int bl = blockIdx.x;
    int b = bl / L_;
    int len = line_lens[bl];
    int start = line_starts[bl];
    float inv = 1.0f / (float)max(len, 1);
    for (int c = threadIdx.x; c < H_; c += 256) {
        float s1 = 0.0f, s2 = 0.0f;
        for (int m = 0; m < ML_; m++) {
            if (m < len) {
                int pos = min(max(start + m, 0), S_ - 1);
                s1 += hidden[((size_t)b * S_ + pos) * H_ + c];
                s2 += oproj[((size_t)bl * ML_ + m) * H_ + c];
            }
        }
        x[(size_t)bl * 2 * H_ + c]      = s1 * inv;
        x[(size_t)bl * 2 * H_ + H_ + c] = s2 * inv;
    }
}

// ---------------- LayerNorm -> exact GELU (+optional residual) ----------------
__global__ __launch_bounds__(256) void ln_gelu_kernel(
    const float* __restrict__ y, const float* __restrict__ g,
    const float* __restrict__ be, const float* __restrict__ res,
    float* __restrict__ out)
{
    __shared__ float red1[8], red2[8];
    int row = blockIdx.x;
    const float* yr = y + (size_t)row * H_;
    float v[3], sum = 0.0f, sq = 0.0f;
#pragma unroll
    for (int i = 0; i < 3; i++) {
        v[i] = yr[threadIdx.x + 256 * i];
        sum += v[i];
        sq  += v[i] * v[i];
    }
#pragma unroll
    for (int o = 16; o > 0; o >>= 1) {
        sum += __shfl_xor_sync(0xffffffffu, sum, o);
        sq  += __shfl_xor_sync(0xffffffffu, sq,  o);
    }
    int warp = threadIdx.x >> 5;
    if ((threadIdx.x & 31) == 0) { red1[warp] = sum; red2[warp] = sq; }
    __syncthreads();
    float tsum = 0.0f, tsq = 0.0f;
#pragma unroll
    for (int i = 0; i < 8; i++) { tsum += red1[i]; tsq += red2[i]; }
    float mean = tsum * (1.0f / H_);
    float var  = tsq  * (1.0f / H_) - mean * mean;
    float rstd = rsqrtf(var + 1e-5f);
#pragma unroll
    for (int i = 0; i < 3; i++) {
        int c = threadIdx.x + 256 * i;
        float t  = (v[i] - mean) * rstd * g[c] + be[c];
        float ge = 0.5f * t * (1.0f + erff(t * 0.70710678118654752f));
        out[(size_t)row * H_ + c] = (res ? res[(size_t)row * H_ + c] : 0.0f) + ge;
    }
}

// ---------------- final logit ----------------
__global__ __launch_bounds__(128) void final_kernel(
    const float* __restrict__ a2, const float* __restrict__ W3,
    const float* __restrict__ b3, const int* __restrict__ line_lens,
    float* __restrict__ out)
{
    int row  = blockIdx.x * 4 + (threadIdx.x >> 5);
    int lane = threadIdx.x & 31;
    float s = 0.0f;
    for (int c = lane; c < H_; c += 32)
        s += a2[(size_t)row * H_ + c] * W3[c];
#pragma unroll
    for (int o = 16; o > 0; o >>= 1) s += __shfl_xor_sync(0xffffffffu, s, o);
    if (lane == 0) {
        float logit = s + b3[0];
        if (line_lens[row] <= 0) logit = -10.0f;
        out[row] = 1.0f / (1.0f + __expf(-logit));
    }
}

// ---------------- launch ----------------
extern "C" void kernel_launch(void* const* d_in, const int* in_sizes, int n_in,
                              void* d_out, int out_size)
{
    (void)in_sizes; (void)n_in; (void)out_size;
    const float* hidden  = (const float*)d_in[0];
    const float* in_w    = (const float*)d_in[1];
    const float* in_b    = (const float*)d_in[2];
    const float* out_w   = (const float*)d_in[3];
    const float* out_b   = (const float*)d_in[4];
    const float* W1      = (const float*)d_in[5];
    const float* b1      = (const float*)d_in[6];
    const float* g1      = (const float*)d_in[7];
    const float* be1     = (const float*)d_in[8];
    const float* W2      = (const float*)d_in[9];
    const float* b2      = (const float*)d_in[10];
    const float* g2      = (const float*)d_in[11];
    const float* be2     = (const float*)d_in[12];
    const float* W3      = (const float*)d_in[13];
    const float* b3      = (const float*)d_in[14];
    const int*   lstarts = (const int*)d_in[15];
    const int*   llens   = (const int*)d_in[16];
    const int*   ctx     = (const int*)d_in[17];
    float* out = (float*)d_out;

    float *qkv, *attn, *oproj, *x, *y1, *y2;
    cudaGetSymbolAddress((void**)&qkv,   g_qkv);
    cudaGetSymbolAddress((void**)&attn,  g_attn);
    cudaGetSymbolAddress((void**)&oproj, g_oproj);
    cudaGetSymbolAddress((void**)&x,     g_x);
    cudaGetSymbolAddress((void**)&y1,    g_y1);
    cudaGetSymbolAddress((void**)&y2,    g_y2);

    // 1) QKV projection (bf16)
    gemm_bf16_nt<<<dim3(QKV_ / 128, (B_ * S_) / 128), 256>>>(hidden, in_w, in_b, qkv,
                                                             B_ * S_, QKV_, H_);
    // 2) cross attention (bf16, 128 queries/CTA, register softmax)
    attn_kernel<<<dim3(LM_ / 128, NH_, B_), 256>>>(qkv, lstarts, ctx, attn);
    // 3) out_proj (bf16)
    gemm_bf16_nt<<<dim3(H_ / 128, (B_ * LM_) / 128), 256>>>(attn, out_w, out_b, oproj,
                                                            B_ * LM_, H_, H_);
    // 4) pooled features
    pool_kernel<<<B_ * L_, 256>>>(hidden, oproj, lstarts, llens, x);
    // 5) classifier head (tf32 for accuracy)
    gemm_tf32_nt<<<dim3(H_ / 128, (B_ * L_) / 128), 256>>>(x, W1, b1, y1, B_ * L_, H_, 2 * H_);
    ln_gelu_kernel<<<B_ * L_, 256>>>(y1, g1, be1, nullptr, y1);
    gemm_tf32_nt<<<dim3(H_ / 128, (B_ * L_) / 128), 256>>>(y1, W2, b2, y2, B_ * L_, H_, H_);
    ln_gelu_kernel<<<B_ * L_, 256>>>(y2, g2, be2, y1, y2);
    final_kernel<<<B_ * L_ / 4, 128>>>(y2, W3, b3, llens, out);
}

// round 8
// speedup vs baseline: 5.3922x; 1.2534x over previous
#include <cuda_runtime.h>
#include <cuda_bf16.h>
#include <math.h>
#include <stdint.h>

// ---------------- problem constants ----------------
#define B_    4
#define S_    2048
#define H_    768
#define NH_   8
#define DH_   96
#define L_    128
#define ML_   15
#define LM_   1920      // L_*ML_
#define QKV_  2304      // 3*H_

// ---------------- scratch ----------------
__device__ __nv_bfloat16 g_hb  [(size_t)B_ * S_ * H_];     // hidden, bf16
__device__ __nv_bfloat16 g_wib [(size_t)QKV_ * H_];        // in_proj_w, bf16
__device__ __nv_bfloat16 g_wob [(size_t)H_ * H_];          // out_proj_w, bf16
__device__ __nv_bfloat16 g_qkvh[(size_t)B_ * S_ * QKV_];   // QKV, bf16 (Q pre-scaled)
__device__ __nv_bfloat16 g_atnh[(size_t)B_ * LM_ * H_];    // attention out, bf16
__device__ float g_oproj[(size_t)B_ * LM_ * H_];
__device__ float g_x    [(size_t)B_ * L_ * 2 * H_];
__device__ float g_y1   [(size_t)B_ * L_ * H_];
__device__ float g_y2   [(size_t)B_ * L_ * H_];

// ---------------- helpers ----------------
__device__ __forceinline__ unsigned pk(float lo, float hi) {
    unsigned r;
    asm("cvt.rn.bf16x2.f32 %0, %1, %2;" : "=r"(r) : "f"(hi), "f"(lo));
    return r;
}
__device__ __forceinline__ float ex2(float x) {
    float r;
    asm("ex2.approx.ftz.f32 %0, %1;" : "=f"(r) : "f"(x));
    return r;
}
__device__ __forceinline__ void mma_bf16(float* d, const unsigned* a, const unsigned* b) {
    asm volatile(
        "mma.sync.aligned.m16n8k16.row.col.f32.bf16.bf16.f32 "
        "{%0,%1,%2,%3}, {%4,%5,%6,%7}, {%8,%9}, {%0,%1,%2,%3};"
        : "+f"(d[0]), "+f"(d[1]), "+f"(d[2]), "+f"(d[3])
        : "r"(a[0]), "r"(a[1]), "r"(a[2]), "r"(a[3]), "r"(b[0]), "r"(b[1]));
}
__device__ __forceinline__ void mma_tf32(float* d, const unsigned* a, const unsigned* b) {
    asm volatile(
        "mma.sync.aligned.m16n8k8.row.col.f32.tf32.tf32.f32 "
        "{%0,%1,%2,%3}, {%4,%5,%6,%7}, {%8,%9}, {%0,%1,%2,%3};"
        : "+f"(d[0]), "+f"(d[1]), "+f"(d[2]), "+f"(d[3])
        : "r"(a[0]), "r"(a[1]), "r"(a[2]), "r"(a[3]), "r"(b[0]), "r"(b[1]));
}
__device__ __forceinline__ uint32_t s2u(const void* p) {
    uint32_t a;
    asm("{ .reg .u64 t; cvta.to.shared.u64 t, %1; cvt.u32.u64 %0, t; }" : "=r"(a) : "l"(p));
    return a;
}
__device__ __forceinline__ void cpa16(uint32_t s, const void* g) {
    asm volatile("cp.async.cg.shared.global [%0], [%1], 16;" :: "r"(s), "l"(g));
}
#define CP_COMMIT() asm volatile("cp.async.commit_group;")
#define CP_WAIT2()  asm volatile("cp.async.wait_group 2;")
__device__ __forceinline__ void ldm4(uint4& d, uint32_t a) {
    asm volatile("ldmatrix.sync.aligned.m8n8.x4.shared.b16 {%0,%1,%2,%3}, [%4];"
                 : "=r"(d.x), "=r"(d.y), "=r"(d.z), "=r"(d.w) : "r"(a));
}

// ---------------- f32 -> bf16 convert (pairs) ----------------
__global__ __launch_bounds__(256) void f2b_kernel(
    const float* __restrict__ src, __nv_bfloat16* __restrict__ dst, int n2)
{
    int stride = gridDim.x * blockDim.x;
    for (int i = blockIdx.x * blockDim.x + threadIdx.x; i < n2; i += stride) {
        float2 v = ((const float2*)src)[i];
        ((unsigned*)dst)[i] = pk(v.x, v.y);
    }
}

// ---------------- bf16 NT GEMM: cp.async 3-stage + ldmatrix ----------------
// C[M,N] = A[M,K] @ B[N,K]^T + bias.  A,B bf16. M%128==0, N%128==0, K%32==0.
// Tile 128x128x32. smem per stage: A 8KB + B 8KB. 3 stages = 48KB.
// Swizzle: 16B chunk c (0..3) of row r stored at c ^ ((r>>1)&3).
__global__ __launch_bounds__(256) void gemm_bf16_cp(
    const __nv_bfloat16* __restrict__ A, const __nv_bfloat16* __restrict__ Bw,
    const float* __restrict__ bias, void* __restrict__ Cout,
    int M, int N, int K, int out_bf16, float qmul, int qcols)
{
    __shared__ __align__(16) char smem[3 * 16384];

    int tid = threadIdx.x;
    int warp = tid >> 5, lane = tid & 31;
    int warp_m = warp >> 1, warp_n = warp & 1;
    int m0 = blockIdx.y * 128, n0 = blockIdx.x * 128;
    uint32_t sbase = s2u(smem);

    float acc[2][8][4];
#pragma unroll
    for (int mi = 0; mi < 2; mi++)
#pragma unroll
        for (int ni = 0; ni < 8; ni++)
#pragma unroll
            for (int r = 0; r < 4; r++) acc[mi][ni][r] = 0.0f;

    int nslab = K >> 5;
    // per-thread fill coords: 512 chunks per matrix per stage, 2 per thread
    int frow0 = tid >> 2,        fc0 = tid & 3;
    int frow1 = (tid + 256) >> 2, fc1 = (tid + 256) & 3;

    // ---- fill stage st with slab sl (A and B, 16B cp.async, swizzled) ----
#define FILL(st, sl)                                                                   \
    do {                                                                               \
        int k0f = (sl) << 5;                                                           \
        uint32_t sa = sbase + (st) * 16384;                                            \
        uint32_t sb = sa + 8192;                                                       \
        cpa16(sa + (frow0 * 4 + (fc0 ^ ((frow0 >> 1) & 3))) * 16,                      \
              A + (size_t)(m0 + frow0) * K + k0f + fc0 * 8);                           \
        cpa16(sa + (frow1 * 4 + (fc1 ^ ((frow1 >> 1) & 3))) * 16,                      \
              A + (size_t)(m0 + frow1) * K + k0f + fc1 * 8);                           \
        cpa16(sb + (frow0 * 4 + (fc0 ^ ((frow0 >> 1) & 3))) * 16,                      \
              Bw + (size_t)(n0 + frow0) * K + k0f + fc0 * 8);                          \
        cpa16(sb + (frow1 * 4 + (fc1 ^ ((frow1 >> 1) & 3))) * 16,                      \
              Bw + (size_t)(n0 + frow1) * K + k0f + fc1 * 8);                          \
    } while (0)

    FILL(0, 0); CP_COMMIT();
    if (nslab > 1) FILL(1, 1);
    CP_COMMIT();

    for (int i = 0; i < nslab; i++) {
        if (i + 2 < nslab) FILL((i + 2) % 3, i + 2);
        CP_COMMIT();
        CP_WAIT2();
        __syncthreads();

        uint32_t sa = sbase + (i % 3) * 16384;
        uint32_t sb = sa + 8192;
#pragma unroll
        for (int ks = 0; ks < 2; ks++) {
            uint4 afr[2];
#pragma unroll
            for (int mi = 0; mi < 2; mi++) {
                int row = warp_m * 32 + mi * 16 + ((lane >> 3) & 1) * 8 + (lane & 7);
                int ch = ks * 2 + (lane >> 4);
                ldm4(afr[mi], sa + (row * 4 + (ch ^ ((row >> 1) & 3))) * 16);
            }
            uint4 bfr[4];
#pragma unroll
            for (int nj = 0; nj < 4; nj++) {
                int row = warp_n * 64 + nj * 16 + ((lane >> 4) & 1) * 8 + (lane & 7);
                int ch = ks * 2 + ((lane >> 3) & 1);
                ldm4(bfr[nj], sb + (row * 4 + (ch ^ ((row >> 1) & 3))) * 16);
            }
#pragma unroll
            for (int mi = 0; mi < 2; mi++)
#pragma unroll
                for (int nj = 0; nj < 4; nj++) {
                    mma_bf16(acc[mi][2 * nj],     (const unsigned*)&afr[mi], &bfr[nj].x);
                    mma_bf16(acc[mi][2 * nj + 1], (const unsigned*)&afr[mi], &bfr[nj].z);
                }
        }
        __syncthreads();
    }
#undef FILL

    // ---- epilogue ----
#pragma unroll
    for (int mi = 0; mi < 2; mi++) {
        int row = m0 + warp_m * 32 + mi * 16 + (lane >> 2);
#pragma unroll
        for (int ni = 0; ni < 8; ni++) {
            int col = n0 + warp_n * 64 + ni * 8 + ((lane & 3) << 1);
            float b0 = bias ? bias[col] : 0.0f;
            float b1 = bias ? bias[col + 1] : 0.0f;
            float v0 = acc[mi][ni][0] + b0, v1 = acc[mi][ni][1] + b1;
            float v2 = acc[mi][ni][2] + b0, v3 = acc[mi][ni][3] + b1;
            if (out_bf16) {
                float s = (col < qcols) ? qmul : 1.0f;
                __nv_bfloat16* Cb = (__nv_bfloat16*)Cout;
                *(unsigned*)(Cb + (size_t)row * N + col)       = pk(v0 * s, v1 * s);
                *(unsigned*)(Cb + (size_t)(row + 8) * N + col) = pk(v2 * s, v3 * s);
            } else {
                float* Cf = (float*)Cout;
                *(float2*)(Cf + (size_t)row * N + col)       = make_float2(v0, v1);
                *(float2*)(Cf + (size_t)(row + 8) * N + col) = make_float2(v2, v3);
            }
        }
    }
}

// ---------------- tf32 NT GEMM (classifier) ----------------
__global__ __launch_bounds__(256) void gemm_tf32_nt(
    const float* __restrict__ A, const float* __restrict__ Bw,
    const float* __restrict__ bias, float* __restrict__ C,
    int M, int N, int K)
{
    __shared__ unsigned As[4 * 8 * 128];
    __shared__ unsigned Bs[4 * 16 * 64];

    int tid = threadIdx.x;
    int warp = tid >> 5, lane = tid & 31;
    int warp_m = warp >> 1, warp_n = warp & 1;
    int m0 = blockIdx.y * 128, n0 = blockIdx.x * 128;

    float acc[2][8][4];
#pragma unroll
    for (int mi = 0; mi < 2; mi++)
#pragma unroll
        for (int ni = 0; ni < 8; ni++)
#pragma unroll
            for (int r = 0; r < 4; r++) acc[mi][ni][r] = 0.0f;

    for (int k0 = 0; k0 < K; k0 += 32) {
        __syncthreads();
#pragma unroll
        for (int i = 0; i < 4; i++) {
            int f = tid + i * 256;
            int row = f >> 3, kq = f & 7;
            float4 v = *(const float4*)(A + (size_t)(m0 + row) * K + k0 + kq * 4);
            int mtile = row >> 4, r = row & 15, ktile = kq >> 1;
            int regb = (r >> 3) + ((kq & 1) << 1);
            unsigned* p = &As[((ktile * 8 + mtile) * 32 + (r & 7) * 4) * 4 + regb];
            p[0]  = __float_as_uint(v.x);
            p[4]  = __float_as_uint(v.y);
            p[8]  = __float_as_uint(v.z);
            p[12] = __float_as_uint(v.w);
        }
#pragma unroll
        for (int i = 0; i < 4; i++) {
            int f = tid + i * 256;
            int row = f >> 3, kq = f & 7;
            float4 v = *(const float4*)(Bw + (size_t)(n0 + row) * K + k0 + kq * 4);
            int ntile = row >> 3, ktile = kq >> 1, reg = kq & 1;
            unsigned* p = &Bs[(ktile * 16 + ntile) * 64 + (row & 7) * 8 + reg];
            p[0] = __float_as_uint(v.x);
            p[2] = __float_as_uint(v.y);
            p[4] = __float_as_uint(v.z);
            p[6] = __float_as_uint(v.w);
        }
        __syncthreads();
#pragma unroll
        for (int ks = 0; ks < 4; ks++) {
            uint4 a[2];
            uint2 b[8];
#pragma unroll
            for (int mi = 0; mi < 2; mi++)
                a[mi] = *(const uint4*)&As[((ks * 8 + warp_m * 2 + mi) * 32 + lane) * 4];
#pragma unroll
            for (int ni = 0; ni < 8; ni++)
                b[ni] = *(const uint2*)&Bs[((ks * 16 + warp_n * 8 + ni) * 32 + lane) * 2];
#pragma unroll
            for (int mi = 0; mi < 2; mi++)
#pragma unroll
                for (int ni = 0; ni < 8; ni++)
                    mma_tf32(acc[mi][ni], (const unsigned*)&a[mi], (const unsigned*)&b[ni]);
        }
    }

#pragma unroll
    for (int mi = 0; mi < 2; mi++) {
        int row = m0 + warp_m * 32 + mi * 16 + (lane >> 2);
#pragma unroll
        for (int ni = 0; ni < 8; ni++) {
            int col = n0 + warp_n * 64 + ni * 8 + ((lane & 3) << 1);
            float b0 = bias ? bias[col] : 0.0f;
            float b1 = bias ? bias[col + 1] : 0.0f;
            *(float2*)(C + (size_t)row * N + col)       = make_float2(acc[mi][ni][0] + b0, acc[mi][ni][1] + b1);
            *(float2*)(C + (size_t)(row + 8) * N + col) = make_float2(acc[mi][ni][2] + b0, acc[mi][ni][3] + b1);
        }
    }
}

// ---------------- bf16 flash cross-attention: QT=128, register softmax ----------------
// qkv is bf16 with Q pre-scaled by scale*log2e. Output written as bf16.
__global__ __launch_bounds__(256) void attn_kernel(
    const __nv_bfloat16* __restrict__ qkv,
    const int* __restrict__ line_starts,
    const int* __restrict__ ctx_len,
    __nv_bfloat16* __restrict__ out)
{
    __shared__ unsigned Ks[6 * 8 * 64];   // K tile frag-order (12KB)
    __shared__ unsigned Vs[4 * 12 * 64];  // V tile frag-order (12KB)

    int tid = threadIdx.x;
    int warp = tid >> 5, lane = tid & 31;
    int b = blockIdx.z, h = blockIdx.y, q0 = blockIdx.x * 128;

    int r0 = warp * 16 + (lane >> 2);
    int c2 = (lane & 3) * 2;
    int ctx = ctx_len[b];

    // ---- Q fragments straight from gmem (bf16, pre-scaled) ----
    const __nv_bfloat16 *qp0, *qp1;
    {
        int gq0 = q0 + r0;
        int l0i = gq0 / ML_, mm0 = gq0 - l0i * ML_;
        int pos0 = min(max(line_starts[b * L_ + l0i] + mm0, 0), S_ - 1);
        int gq1 = gq0 + 8;
        int l1i = gq1 / ML_, mm1 = gq1 - l1i * ML_;
        int pos1 = min(max(line_starts[b * L_ + l1i] + mm1, 0), S_ - 1);
        qp0 = qkv + ((size_t)b * S_ + pos0) * QKV_ + h * DH_;
        qp1 = qkv + ((size_t)b * S_ + pos1) * QKV_ + h * DH_;
    }
    unsigned qf[6][4];
#pragma unroll
    for (int ks = 0; ks < 6; ks++) {
        qf[ks][0] = *(const unsigned*)(qp0 + ks * 16 + c2);
        qf[ks][1] = *(const unsigned*)(qp1 + ks * 16 + c2);
        qf[ks][2] = *(const unsigned*)(qp0 + ks * 16 + c2 + 8);
        qf[ks][3] = *(const unsigned*)(qp1 + ks * 16 + c2 + 8);
    }

    float m0 = -1e30f, m1 = -1e30f, l0 = 0.0f, l1 = 0.0f;
    float Oacc[12][4];
#pragma unroll
    for (int nt = 0; nt < 12; nt++)
#pragma unroll
        for (int r = 0; r < 4; r++) Oacc[nt][r] = 0.0f;

    for (int s0 = 0; s0 < S_; s0 += 64) {
        // ---- K fill: 64 tok x 96 d, bf16 pairs are direct word moves ----
#pragma unroll
        for (int i = 0; i < 6; i++) {
            int u = tid + i * 256;
            int tok = u / 24, dq = u - tok * 24;
            uint2 v = *(const uint2*)(qkv + ((size_t)b * S_ + s0 + tok) * QKV_ + H_ + h * DH_ + dq * 4);
            int kt = dq >> 2, pp = 2 * (dq & 3);
            int base = ((kt * 8 + (tok >> 3)) * 32 + (tok & 7) * 4);
            int h2 = pp >> 2;
            Ks[(base + (pp & 3)) * 2 + h2]       = v.x;
            Ks[(base + ((pp + 1) & 3)) * 2 + h2] = v.y;
        }
        // ---- V fill: token-pair transpose via byte_perm ----
#pragma unroll
        for (int i = 0; i < 6; i++) {
            int u = tid + i * 256;
            int j = u % 48, r = u / 48;
            int pq = r & 7, tt = r >> 3;
            int t0 = s0 + tt * 16 + pq * 2;
            const __nv_bfloat16* vptr = qkv + ((size_t)b * S_ + t0) * QKV_ + 2 * H_ + h * DH_ + 2 * j;
            unsigned va = *(const unsigned*)(vptr);
            unsigned vb = *(const unsigned*)(vptr + QKV_);
            int d0 = 2 * j, c = pq & 3, rg = pq >> 2;
            Vs[((tt * 12 + (d0 >> 3)) * 32 + (d0 & 7) * 4 + c) * 2 + rg] = __byte_perm(va, vb, 0x5410);
            int d1 = d0 + 1;
            Vs[((tt * 12 + (d1 >> 3)) * 32 + (d1 & 7) * 4 + c) * 2 + rg] = __byte_perm(va, vb, 0x7632);
        }
        __syncthreads();

        // ---- scores: 16q x 64tok per warp ----
        float sacc[8][4];
#pragma unroll
        for (int nt = 0; nt < 8; nt++)
#pragma unroll
            for (int r = 0; r < 4; r++) sacc[nt][r] = 0.0f;
#pragma unroll
        for (int ks = 0; ks < 6; ks++) {
#pragma unroll
            for (int nt = 0; nt < 8; nt++) {
                uint2 kb = *(const uint2*)&Ks[((ks * 8 + nt) * 32 + lane) * 2];
                mma_bf16(sacc[nt], qf[ks], (const unsigned*)&kb);
            }
        }

        // ---- register softmax (online) ----
        float mx0 = -1e30f, mx1 = -1e30f;
#pragma unroll
        for (int nt = 0; nt < 8; nt++) {
            int t = s0 + nt * 8 + c2;
            if (t >= ctx)     { sacc[nt][0] = -1e30f; sacc[nt][2] = -1e30f; }
            if (t + 1 >= ctx) { sacc[nt][1] = -1e30f; sacc[nt][3] = -1e30f; }
            mx0 = fmaxf(mx0, fmaxf(sacc[nt][0], sacc[nt][1]));
            mx1 = fmaxf(mx1, fmaxf(sacc[nt][2], sacc[nt][3]));
        }
        mx0 = fmaxf(mx0, __shfl_xor_sync(0xffffffffu, mx0, 1));
        mx0 = fmaxf(mx0, __shfl_xor_sync(0xffffffffu, mx0, 2));
        mx1 = fmaxf(mx1, __shfl_xor_sync(0xffffffffu, mx1, 1));
        mx1 = fmaxf(mx1, __shfl_xor_sync(0xffffffffu, mx1, 2));
        float mn0 = fmaxf(m0, mx0), mn1 = fmaxf(m1, mx1);
        float fac0 = ex2(m0 - mn0), fac1 = ex2(m1 - mn1);
        float sum0 = 0.0f, sum1 = 0.0f;
#pragma unroll
        for (int nt = 0; nt < 8; nt++) {
            int t = s0 + nt * 8 + c2;
            float p0 = (t < ctx)     ? ex2(sacc[nt][0] - mn0) : 0.0f;
            float p1 = (t + 1 < ctx) ? ex2(sacc[nt][1] - mn0) : 0.0f;
            float p2 = (t < ctx)     ? ex2(sacc[nt][2] - mn1) : 0.0f;
            float p3 = (t + 1 < ctx) ? ex2(sacc[nt][3] - mn1) : 0.0f;
            sacc[nt][0] = p0; sacc[nt][1] = p1; sacc[nt][2] = p2; sacc[nt][3] = p3;
            sum0 += p0 + p1;
            sum1 += p2 + p3;
        }
        sum0 += __shfl_xor_sync(0xffffffffu, sum0, 1);
        sum0 += __shfl_xor_sync(0xffffffffu, sum0, 2);
        sum1 += __shfl_xor_sync(0xffffffffu, sum1, 1);
        sum1 += __shfl_xor_sync(0xffffffffu, sum1, 2);
        l0 = l0 * fac0 + sum0;  m0 = mn0;
        l1 = l1 * fac1 + sum1;  m1 = mn1;

        // ---- rescale + P@V ----
#pragma unroll
        for (int nt = 0; nt < 12; nt++) {
            Oacc[nt][0] *= fac0; Oacc[nt][1] *= fac0;
            Oacc[nt][2] *= fac1; Oacc[nt][3] *= fac1;
        }
#pragma unroll
        for (int ks = 0; ks < 4; ks++) {
            unsigned pa[4];
            pa[0] = pk(sacc[2 * ks][0],     sacc[2 * ks][1]);
            pa[1] = pk(sacc[2 * ks][2],     sacc[2 * ks][3]);
            pa[2] = pk(sacc[2 * ks + 1][0], sacc[2 * ks + 1][1]);
            pa[3] = pk(sacc[2 * ks + 1][2], sacc[2 * ks + 1][3]);
#pragma unroll
            for (int nt = 0; nt < 12; nt++) {
                uint2 vb2 = *(const uint2*)&Vs[((ks * 12 + nt) * 32 + lane) * 2];
                mma_bf16(Oacc[nt], pa, (const unsigned*)&vb2);
            }
        }
        __syncthreads();
    }

    // ---- epilogue: bf16 store (identical rounding to old out_proj fill) ----
    float inv0 = 1.0f / l0;
    float inv1 = 1.0f / l1;
#pragma unroll
    for (int nt = 0; nt < 12; nt++) {
        int col = h * DH_ + nt * 8 + c2;
        *(unsigned*)(out + ((size_t)b * LM_ + q0 + r0) * H_ + col) =
            pk(Oacc[nt][0] * inv0, Oacc[nt][1] * inv0);
        *(unsigned*)(out + ((size_t)b * LM_ + q0 + r0 + 8) * H_ + col) =
            pk(Oacc[nt][2] * inv1, Oacc[nt][3] * inv1);
    }
}

// ---------------- masked mean-pool ----------------
__global__ __launch_bounds__(256) void pool_kernel(
    const float* __restrict__ hidden, const float* __restrict__ oproj,
    const int* __restrict__ line_starts, const int* __restrict__ line_lens,
    float* __restrict__ x)
{
    int bl = blockIdx.x;
    int b = bl / L_;
    int len = line_lens[bl];
    int start = line_starts[bl];
    float inv = 1.0f / (float)max(len, 1);
    for (int c = threadIdx.x; c < H_; c += 256) {
        float s1 = 0.0f, s2 = 0.0f;
        for (int m = 0; m < ML_; m++) {
            if (m < len) {
                int pos = min(max(start + m, 0), S_ - 1);
                s1 += hidden[((size_t)b * S_ + pos) * H_ + c];
                s2 += oproj[((size_t)bl * ML_ + m) * H_ + c];
            }
        }
        x[(size_t)bl * 2 * H_ + c]      = s1 * inv;
        x[(size_t)bl * 2 * H_ + H_ + c] = s2 * inv;
    }
}

// ---------------- LayerNorm -> exact GELU (+optional residual) ----------------
__global__ __launch_bounds__(256) void ln_gelu_kernel(
    const float* __restrict__ y, const float* __restrict__ g,
    const float* __restrict__ be, const float* __restrict__ res,
    float* __restrict__ out)
{
    __shared__ float red1[8], red2[8];
    int row = blockIdx.x;
    const float* yr = y + (size_t)row * H_;
    float v[3], sum = 0.0f, sq = 0.0f;
#pragma unroll
    for (int i = 0; i < 3; i++) {
        v[i] = yr[threadIdx.x + 256 * i];
        sum += v[i];
        sq  += v[i] * v[i];
    }
#pragma unroll
    for (int o = 16; o > 0; o >>= 1) {
        sum += __shfl_xor_sync(0xffffffffu, sum, o);
        sq  += __shfl_xor_sync(0xffffffffu, sq,  o);
    }
    int warp = threadIdx.x >> 5;
    if ((threadIdx.x & 31) == 0) { red1[warp] = sum; red2[warp] = sq; }
    __syncthreads();
    float tsum = 0.0f, tsq = 0.0f;
#pragma unroll
    for (int i = 0; i < 8; i++) { tsum += red1[i]; tsq += red2[i]; }
    float mean = tsum * (1.0f / H_);
    float var  = tsq  * (1.0f / H_) - mean * mean;
    float rstd = rsqrtf(var + 1e-5f);
#pragma unroll
    for (int i = 0; i < 3; i++) {
        int c = threadIdx.x + 256 * i;
        float t  = (v[i] - mean) * rstd * g[c] + be[c];
        float ge = 0.5f * t * (1.0f + erff(t * 0.70710678118654752f));
        out[(size_t)row * H_ + c] = (res ? res[(size_t)row * H_ + c] : 0.0f) + ge;
    }
}

// ---------------- final logit ----------------
__global__ __launch_bounds__(128) void final_kernel(
    const float* __restrict__ a2, const float* __restrict__ W3,
    const float* __restrict__ b3, const int* __restrict__ line_lens,
    float* __restrict__ out)
{
    int row  = blockIdx.x * 4 + (threadIdx.x >> 5);
    int lane = threadIdx.x & 31;
    float s = 0.0f;
    for (int c = lane; c < H_; c += 32)
        s += a2[(size_t)row * H_ + c] * W3[c];
#pragma unroll
    for (int o = 16; o > 0; o >>= 1) s += __shfl_xor_sync(0xffffffffu, s, o);
    if (lane == 0) {
        float logit = s + b3[0];
        if (line_lens[row] <= 0) logit = -10.0f;
        out[row] = 1.0f / (1.0f + __expf(-logit));
    }
}

// ---------------- launch ----------------
extern "C" void kernel_launch(void* const* d_in, const int* in_sizes, int n_in,
                              void* d_out, int out_size)
{
    (void)in_sizes; (void)n_in; (void)out_size;
    const float* hidden  = (const float*)d_in[0];
    const float* in_w    = (const float*)d_in[1];
    const float* in_b    = (const float*)d_in[2];
    const float* out_w   = (const float*)d_in[3];
    const float* out_b   = (const float*)d_in[4];
    const float* W1      = (const float*)d_in[5];
    const float* b1      = (const float*)d_in[6];
    const float* g1      = (const float*)d_in[7];
    const float* be1     = (const float*)d_in[8];
    const float* W2      = (const float*)d_in[9];
    const float* b2      = (const float*)d_in[10];
    const float* g2      = (const float*)d_in[11];
    const float* be2     = (const float*)d_in[12];
    const float* W3      = (const float*)d_in[13];
    const float* b3      = (const float*)d_in[14];
    const int*   lstarts = (const int*)d_in[15];
    const int*   llens   = (const int*)d_in[16];
    const int*   ctx     = (const int*)d_in[17];
    float* out = (float*)d_out;

    __nv_bfloat16 *hb, *wib, *wob, *qkvh, *atnh;
    float *oproj, *x, *y1, *y2;
    cudaGetSymbolAddress((void**)&hb,    g_hb);
    cudaGetSymbolAddress((void**)&wib,   g_wib);
    cudaGetSymbolAddress((void**)&wob,   g_wob);
    cudaGetSymbolAddress((void**)&qkvh,  g_qkvh);
    cudaGetSymbolAddress((void**)&atnh,  g_atnh);
    cudaGetSymbolAddress((void**)&oproj, g_oproj);
    cudaGetSymbolAddress((void**)&x,     g_x);
    cudaGetSymbolAddress((void**)&y1,    g_y1);
    cudaGetSymbolAddress((void**)&y2,    g_y2);

    const float qmul = 0.10206207261596577f * 1.4426950408889634f;  // 1/sqrt(96)*log2e

    // 0) one-time f32->bf16 converts (same rounding the old fills did)
    f2b_kernel<<<2048, 256>>>(hidden, hb,  (B_ * S_ * H_) / 2);
    f2b_kernel<<<1024, 256>>>(in_w,  wib, (QKV_ * H_) / 2);
    f2b_kernel<<<512,  256>>>(out_w, wob, (H_ * H_) / 2);

    // 1) QKV projection (bf16 out, Q columns pre-scaled)
    gemm_bf16_cp<<<dim3(QKV_ / 128, (B_ * S_) / 128), 256>>>(
        hb, wib, in_b, qkvh, B_ * S_, QKV_, H_, 1, qmul, H_);
    // 2) cross attention (bf16 in/out)
    attn_kernel<<<dim3(LM_ / 128, NH_, B_), 256>>>(qkvh, lstarts, ctx, atnh);
    // 3) out_proj (bf16 in, f32 out)
    gemm_bf16_cp<<<dim3(H_ / 128, (B_ * LM_) / 128), 256>>>(
        atnh, wob, out_b, oproj, B_ * LM_, H_, H_, 0, 1.0f, 0);
    // 4) pooled features
    pool_kernel<<<B_ * L_, 256>>>(hidden, oproj, lstarts, llens, x);
    // 5) classifier head (tf32)
    gemm_tf32_nt<<<dim3(H_ / 128, (B_ * L_) / 128), 256>>>(x, W1, b1, y1, B_ * L_, H_, 2 * H_);
    ln_gelu_kernel<<<B_ * L_, 256>>>(y1, g1, be1, nullptr, y1);
    gemm_tf32_nt<<<dim3(H_ / 128, (B_ * L_) / 128), 256>>>(y1, W2, b2, y2, B_ * L_, H_, H_);
    ln_gelu_kernel<<<B_ * L_, 256>>>(y2, g2, be2, y1, y2);
    final_kernel<<<B_ * L_ / 4, 128>>>(y2, W3, b3, llens, out);
}

// round 9
// speedup vs baseline: 5.8137x; 1.0782x over previous
#include <cuda_runtime.h>
#include <cuda_bf16.h>
#include <math.h>
#include <stdint.h>

// ---------------- problem constants ----------------
#define B_    4
#define S_    2048
#define H_    768
#define NH_   8
#define DH_   96
#define L_    128
#define ML_   15
#define LM_   1920      // L_*ML_
#define QKV_  2304      // 3*H_

// ---------------- scratch ----------------
__device__ __nv_bfloat16 g_hb  [(size_t)B_ * S_ * H_];     // hidden, bf16
__device__ __nv_bfloat16 g_wib [(size_t)QKV_ * H_];        // in_proj_w, bf16
__device__ __nv_bfloat16 g_wob [(size_t)H_ * H_];          // out_proj_w, bf16
__device__ __nv_bfloat16 g_qkvh[(size_t)B_ * S_ * QKV_];   // QKV, bf16 (Q pre-scaled)
__device__ __nv_bfloat16 g_atnh[(size_t)B_ * LM_ * H_];    // attention out, bf16
__device__ float g_oproj[(size_t)B_ * LM_ * H_];
__device__ float g_x    [(size_t)B_ * L_ * 2 * H_];
__device__ float g_y1   [(size_t)B_ * L_ * H_];
__device__ float g_y2   [(size_t)B_ * L_ * H_];

// ---------------- helpers ----------------
__device__ __forceinline__ unsigned pk(float lo, float hi) {
    unsigned r;
    asm("cvt.rn.bf16x2.f32 %0, %1, %2;" : "=r"(r) : "f"(hi), "f"(lo));
    return r;
}
__device__ __forceinline__ float ex2(float x) {
    float r;
    asm("ex2.approx.ftz.f32 %0, %1;" : "=f"(r) : "f"(x));
    return r;
}
__device__ __forceinline__ unsigned bex2(unsigned x) {   // two bf16 exps at once
    unsigned r;
    asm("ex2.approx.ftz.bf16x2 %0, %1;" : "=r"(r) : "r"(x));
    return r;
}
__device__ __forceinline__ void mma_bf16(float* d, const unsigned* a, const unsigned* b) {
    asm volatile(
        "mma.sync.aligned.m16n8k16.row.col.f32.bf16.bf16.f32 "
        "{%0,%1,%2,%3}, {%4,%5,%6,%7}, {%8,%9}, {%0,%1,%2,%3};"
        : "+f"(d[0]), "+f"(d[1]), "+f"(d[2]), "+f"(d[3])
        : "r"(a[0]), "r"(a[1]), "r"(a[2]), "r"(a[3]), "r"(b[0]), "r"(b[1]));
}
__device__ __forceinline__ void mma_tf32(float* d, const unsigned* a, const unsigned* b) {
    asm volatile(
        "mma.sync.aligned.m16n8k8.row.col.f32.tf32.tf32.f32 "
        "{%0,%1,%2,%3}, {%4,%5,%6,%7}, {%8,%9}, {%0,%1,%2,%3};"
        : "+f"(d[0]), "+f"(d[1]), "+f"(d[2]), "+f"(d[3])
        : "r"(a[0]), "r"(a[1]), "r"(a[2]), "r"(a[3]), "r"(b[0]), "r"(b[1]));
}
__device__ __forceinline__ uint32_t s2u(const void* p) {
    uint32_t a;
    asm("{ .reg .u64 t; cvta.to.shared.u64 t, %1; cvt.u32.u64 %0, t; }" : "=r"(a) : "l"(p));
    return a;
}
__device__ __forceinline__ void cpa16(uint32_t s, const void* g) {
    asm volatile("cp.async.cg.shared.global [%0], [%1], 16;" :: "r"(s), "l"(g));
}
#define CP_COMMIT() asm volatile("cp.async.commit_group;")
#define CP_WAIT2()  asm volatile("cp.async.wait_group 2;")
__device__ __forceinline__ void ldm4(uint4& d, uint32_t a) {
    asm volatile("ldmatrix.sync.aligned.m8n8.x4.shared.b16 {%0,%1,%2,%3}, [%4];"
                 : "=r"(d.x), "=r"(d.y), "=r"(d.z), "=r"(d.w) : "r"(a));
}

// ---------------- f32 -> bf16 convert (pairs) ----------------
__global__ __launch_bounds__(256) void f2b_kernel(
    const float* __restrict__ src, __nv_bfloat16* __restrict__ dst, int n2)
{
    int stride = gridDim.x * blockDim.x;
    for (int i = blockIdx.x * blockDim.x + threadIdx.x; i < n2; i += stride) {
        float2 v = ((const float2*)src)[i];
        ((unsigned*)dst)[i] = pk(v.x, v.y);
    }
}

// ---------------- bf16 NT GEMM: cp.async 3-stage + ldmatrix ----------------
__global__ __launch_bounds__(256) void gemm_bf16_cp(
    const __nv_bfloat16* __restrict__ A, const __nv_bfloat16* __restrict__ Bw,
    const float* __restrict__ bias, void* __restrict__ Cout,
    int M, int N, int K, int out_bf16, float qmul, int qcols)
{
    __shared__ __align__(16) char smem[3 * 16384];

    int tid = threadIdx.x;
    int warp = tid >> 5, lane = tid & 31;
    int warp_m = warp >> 1, warp_n = warp & 1;
    int m0 = blockIdx.y * 128, n0 = blockIdx.x * 128;
    uint32_t sbase = s2u(smem);

    float acc[2][8][4];
#pragma unroll
    for (int mi = 0; mi < 2; mi++)
#pragma unroll
        for (int ni = 0; ni < 8; ni++)
#pragma unroll
            for (int r = 0; r < 4; r++) acc[mi][ni][r] = 0.0f;

    int nslab = K >> 5;
    int frow0 = tid >> 2,        fc0 = tid & 3;
    int frow1 = (tid + 256) >> 2, fc1 = (tid + 256) & 3;

#define FILL(st, sl)                                                                   \
    do {                                                                               \
        int k0f = (sl) << 5;                                                           \
        uint32_t sa = sbase + (st) * 16384;                                            \
        uint32_t sb = sa + 8192;                                                       \
        cpa16(sa + (frow0 * 4 + (fc0 ^ ((frow0 >> 1) & 3))) * 16,                      \
              A + (size_t)(m0 + frow0) * K + k0f + fc0 * 8);                           \
        cpa16(sa + (frow1 * 4 + (fc1 ^ ((frow1 >> 1) & 3))) * 16,                      \
              A + (size_t)(m0 + frow1) * K + k0f + fc1 * 8);                           \
        cpa16(sb + (frow0 * 4 + (fc0 ^ ((frow0 >> 1) & 3))) * 16,                      \
              Bw + (size_t)(n0 + frow0) * K + k0f + fc0 * 8);                          \
        cpa16(sb + (frow1 * 4 + (fc1 ^ ((frow1 >> 1) & 3))) * 16,                      \
              Bw + (size_t)(n0 + frow1) * K + k0f + fc1 * 8);                          \
    } while (0)

    FILL(0, 0); CP_COMMIT();
    if (nslab > 1) FILL(1, 1);
    CP_COMMIT();

    for (int i = 0; i < nslab; i++) {
        if (i + 2 < nslab) FILL((i + 2) % 3, i + 2);
        CP_COMMIT();
        CP_WAIT2();
        __syncthreads();

        uint32_t sa = sbase + (i % 3) * 16384;
        uint32_t sb = sa + 8192;
#pragma unroll
        for (int ks = 0; ks < 2; ks++) {
            uint4 afr[2];
#pragma unroll
            for (int mi = 0; mi < 2; mi++) {
                int row = warp_m * 32 + mi * 16 + ((lane >> 3) & 1) * 8 + (lane & 7);
                int ch = ks * 2 + (lane >> 4);
                ldm4(afr[mi], sa + (row * 4 + (ch ^ ((row >> 1) & 3))) * 16);
            }
            uint4 bfr[4];
#pragma unroll
            for (int nj = 0; nj < 4; nj++) {
                int row = warp_n * 64 + nj * 16 + ((lane >> 4) & 1) * 8 + (lane & 7);
                int ch = ks * 2 + ((lane >> 3) & 1);
                ldm4(bfr[nj], sb + (row * 4 + (ch ^ ((row >> 1) & 3))) * 16);
            }
#pragma unroll
            for (int mi = 0; mi < 2; mi++)
#pragma unroll
                for (int nj = 0; nj < 4; nj++) {
                    mma_bf16(acc[mi][2 * nj],     (const unsigned*)&afr[mi], &bfr[nj].x);
                    mma_bf16(acc[mi][2 * nj + 1], (const unsigned*)&afr[mi], &bfr[nj].z);
                }
        }
        __syncthreads();
    }
#undef FILL

#pragma unroll
    for (int mi = 0; mi < 2; mi++) {
        int row = m0 + warp_m * 32 + mi * 16 + (lane >> 2);
#pragma unroll
        for (int ni = 0; ni < 8; ni++) {
            int col = n0 + warp_n * 64 + ni * 8 + ((lane & 3) << 1);
            float b0 = bias ? bias[col] : 0.0f;
            float b1 = bias ? bias[col + 1] : 0.0f;
            float v0 = acc[mi][ni][0] + b0, v1 = acc[mi][ni][1] + b1;
            float v2 = acc[mi][ni][2] + b0, v3 = acc[mi][ni][3] + b1;
            if (out_bf16) {
                float s = (col < qcols) ? qmul : 1.0f;
                __nv_bfloat16* Cb = (__nv_bfloat16*)Cout;
                *(unsigned*)(Cb + (size_t)row * N + col)       = pk(v0 * s, v1 * s);
                *(unsigned*)(Cb + (size_t)(row + 8) * N + col) = pk(v2 * s, v3 * s);
            } else {
                float* Cf = (float*)Cout;
                *(float2*)(Cf + (size_t)row * N + col)       = make_float2(v0, v1);
                *(float2*)(Cf + (size_t)(row + 8) * N + col) = make_float2(v2, v3);
            }
        }
    }
}

// ---------------- tf32 NT GEMM (classifier) ----------------
__global__ __launch_bounds__(256) void gemm_tf32_nt(
    const float* __restrict__ A, const float* __restrict__ Bw,
    const float* __restrict__ bias, float* __restrict__ C,
    int M, int N, int K)
{
    __shared__ unsigned As[4 * 8 * 128];
    __shared__ unsigned Bs[4 * 16 * 64];

    int tid = threadIdx.x;
    int warp = tid >> 5, lane = tid & 31;
    int warp_m = warp >> 1, warp_n = warp & 1;
    int m0 = blockIdx.y * 128, n0 = blockIdx.x * 128;

    float acc[2][8][4];
#pragma unroll
    for (int mi = 0; mi < 2; mi++)
#pragma unroll
        for (int ni = 0; ni < 8; ni++)
#pragma unroll
            for (int r = 0; r < 4; r++) acc[mi][ni][r] = 0.0f;

    for (int k0 = 0; k0 < K; k0 += 32) {
        __syncthreads();
#pragma unroll
        for (int i = 0; i < 4; i++) {
            int f = tid + i * 256;
            int row = f >> 3, kq = f & 7;
            float4 v = *(const float4*)(A + (size_t)(m0 + row) * K + k0 + kq * 4);
            int mtile = row >> 4, r = row & 15, ktile = kq >> 1;
            int regb = (r >> 3) + ((kq & 1) << 1);
            unsigned* p = &As[((ktile * 8 + mtile) * 32 + (r & 7) * 4) * 4 + regb];
            p[0]  = __float_as_uint(v.x);
            p[4]  = __float_as_uint(v.y);
            p[8]  = __float_as_uint(v.z);
            p[12] = __float_as_uint(v.w);
        }
#pragma unroll
        for (int i = 0; i < 4; i++) {
            int f = tid + i * 256;
            int row = f >> 3, kq = f & 7;
            float4 v = *(const float4*)(Bw + (size_t)(n0 + row) * K + k0 + kq * 4);
            int ntile = row >> 3, ktile = kq >> 1, reg = kq & 1;
            unsigned* p = &Bs[(ktile * 16 + ntile) * 64 + (row & 7) * 8 + reg];
            p[0] = __float_as_uint(v.x);
            p[2] = __float_as_uint(v.y);
            p[4] = __float_as_uint(v.z);
            p[6] = __float_as_uint(v.w);
        }
        __syncthreads();
#pragma unroll
        for (int ks = 0; ks < 4; ks++) {
            uint4 a[2];
            uint2 b[8];
#pragma unroll
            for (int mi = 0; mi < 2; mi++)
                a[mi] = *(const uint4*)&As[((ks * 8 + warp_m * 2 + mi) * 32 + lane) * 4];
#pragma unroll
            for (int ni = 0; ni < 8; ni++)
                b[ni] = *(const uint2*)&Bs[((ks * 16 + warp_n * 8 + ni) * 32 + lane) * 2];
#pragma unroll
            for (int mi = 0; mi < 2; mi++)
#pragma unroll
                for (int ni = 0; ni < 8; ni++)
                    mma_tf32(acc[mi][ni], (const unsigned*)&a[mi], (const unsigned*)&b[ni]);
        }
    }

#pragma unroll
    for (int mi = 0; mi < 2; mi++) {
        int row = m0 + warp_m * 32 + mi * 16 + (lane >> 2);
#pragma unroll
        for (int ni = 0; ni < 8; ni++) {
            int col = n0 + warp_n * 64 + ni * 8 + ((lane & 3) << 1);
            float b0 = bias ? bias[col] : 0.0f;
            float b1 = bias ? bias[col + 1] : 0.0f;
            *(float2*)(C + (size_t)row * N + col)       = make_float2(acc[mi][ni][0] + b0, acc[mi][ni][1] + b1);
            *(float2*)(C + (size_t)(row + 8) * N + col) = make_float2(acc[mi][ni][2] + b0, acc[mi][ni][3] + b1);
        }
    }
}

// ---------------- bf16 flash cross-attention ----------------
// QT=128, register softmax, paired bf16x2 exp, row-sum l via ones-column of V.
__global__ __launch_bounds__(256, 2) void attn_kernel(
    const __nv_bfloat16* __restrict__ qkv,
    const int* __restrict__ line_starts,
    const int* __restrict__ ctx_len,
    __nv_bfloat16* __restrict__ out)
{
    __shared__ unsigned Ks[6 * 8 * 64];    // K tile frag-order (12KB)
    __shared__ unsigned Vs[4 * 13 * 64];   // V tile frag-order + ones column (13KB)

    int tid = threadIdx.x;
    int warp = tid >> 5, lane = tid & 31;
    int b = blockIdx.z, h = blockIdx.y, q0 = blockIdx.x * 128;

    int r0 = warp * 16 + (lane >> 2);
    int c2 = (lane & 3) * 2;
    int ctx = ctx_len[b];

    // ---- ones-column init (V n-tile 12: col 96 = 1.0, cols 97..103 = 0) ----
    {
        int tt = tid >> 6, laneb = (tid >> 1) & 31, rg = tid & 1;
        Vs[((tt * 13 + 12) * 32 + laneb) * 2 + rg] = (laneb < 4) ? 0x3F803F80u : 0u;
    }

    // ---- Q fragments straight from gmem (bf16, pre-scaled) ----
    const __nv_bfloat16 *qp0, *qp1;
    {
        int gq0 = q0 + r0;
        int l0i = gq0 / ML_, mm0 = gq0 - l0i * ML_;
        int pos0 = min(max(line_starts[b * L_ + l0i] + mm0, 0), S_ - 1);
        int gq1 = gq0 + 8;
        int l1i = gq1 / ML_, mm1 = gq1 - l1i * ML_;
        int pos1 = min(max(line_starts[b * L_ + l1i] + mm1, 0), S_ - 1);
        qp0 = qkv + ((size_t)b * S_ + pos0) * QKV_ + h * DH_;
        qp1 = qkv + ((size_t)b * S_ + pos1) * QKV_ + h * DH_;
    }
    unsigned qf[6][4];
#pragma unroll
    for (int ks = 0; ks < 6; ks++) {
        qf[ks][0] = *(const unsigned*)(qp0 + ks * 16 + c2);
        qf[ks][1] = *(const unsigned*)(qp1 + ks * 16 + c2);
        qf[ks][2] = *(const unsigned*)(qp0 + ks * 16 + c2 + 8);
        qf[ks][3] = *(const unsigned*)(qp1 + ks * 16 + c2 + 8);
    }

    float m0 = -1e30f, m1 = -1e30f;
    float Oacc[13][4];     // [12] = l column
#pragma unroll
    for (int nt = 0; nt < 13; nt++)
#pragma unroll
        for (int r = 0; r < 4; r++) Oacc[nt][r] = 0.0f;

    for (int s0 = 0; s0 < S_; s0 += 64) {
        // ---- K fill ----
#pragma unroll
        for (int i = 0; i < 6; i++) {
            int u = tid + i * 256;
            int tok = u / 24, dq = u - tok * 24;
            uint2 v = *(const uint2*)(qkv + ((size_t)b * S_ + s0 + tok) * QKV_ + H_ + h * DH_ + dq * 4);
            int kt = dq >> 2, pp = 2 * (dq & 3);
            int base = ((kt * 8 + (tok >> 3)) * 32 + (tok & 7) * 4);
            int h2 = pp >> 2;
            Ks[(base + (pp & 3)) * 2 + h2]       = v.x;
            Ks[(base + ((pp + 1) & 3)) * 2 + h2] = v.y;
        }
        // ---- V fill (n-tiles 0..11; tile 12 is the static ones column) ----
#pragma unroll
        for (int i = 0; i < 6; i++) {
            int u = tid + i * 256;
            int j = u % 48, r = u / 48;
            int pq = r & 7, tt = r >> 3;
            int t0 = s0 + tt * 16 + pq * 2;
            const __nv_bfloat16* vptr = qkv + ((size_t)b * S_ + t0) * QKV_ + 2 * H_ + h * DH_ + 2 * j;
            unsigned va = *(const unsigned*)(vptr);
            unsigned vb = *(const unsigned*)(vptr + QKV_);
            int d0 = 2 * j, c = pq & 3, rg = pq >> 2;
            Vs[((tt * 13 + (d0 >> 3)) * 32 + (d0 & 7) * 4 + c) * 2 + rg] = __byte_perm(va, vb, 0x5410);
            int d1 = d0 + 1;
            Vs[((tt * 13 + (d1 >> 3)) * 32 + (d1 & 7) * 4 + c) * 2 + rg] = __byte_perm(va, vb, 0x7632);
        }
        __syncthreads();

        // ---- scores: 16q x 64tok per warp ----
        float sacc[8][4];
#pragma unroll
        for (int nt = 0; nt < 8; nt++)
#pragma unroll
            for (int r = 0; r < 4; r++) sacc[nt][r] = 0.0f;
#pragma unroll
        for (int ks = 0; ks < 6; ks++) {
#pragma unroll
            for (int nt = 0; nt < 8; nt++) {
                uint2 kb = *(const uint2*)&Ks[((ks * 8 + nt) * 32 + lane) * 2];
                mma_bf16(sacc[nt], qf[ks], (const unsigned*)&kb);
            }
        }

        // ---- mask + running max ----
        float mx0 = -3e38f, mx1 = -3e38f;
#pragma unroll
        for (int nt = 0; nt < 8; nt++) {
            int t = s0 + nt * 8 + c2;
            if (t >= ctx)     { sacc[nt][0] = -3e38f; sacc[nt][2] = -3e38f; }
            if (t + 1 >= ctx) { sacc[nt][1] = -3e38f; sacc[nt][3] = -3e38f; }
            mx0 = fmaxf(mx0, fmaxf(sacc[nt][0], sacc[nt][1]));
            mx1 = fmaxf(mx1, fmaxf(sacc[nt][2], sacc[nt][3]));
        }
        mx0 = fmaxf(mx0, __shfl_xor_sync(0xffffffffu, mx0, 1));
        mx0 = fmaxf(mx0, __shfl_xor_sync(0xffffffffu, mx0, 2));
        mx1 = fmaxf(mx1, __shfl_xor_sync(0xffffffffu, mx1, 1));
        mx1 = fmaxf(mx1, __shfl_xor_sync(0xffffffffu, mx1, 2));
        float mn0 = fmaxf(m0, mx0), mn1 = fmaxf(m1, mx1);
        float fac0 = ex2(m0 - mn0), fac1 = ex2(m1 - mn1);
        m0 = mn0; m1 = mn1;

        // ---- rescale all 13 columns (includes the l column: online l update) ----
#pragma unroll
        for (int nt = 0; nt < 13; nt++) {
            Oacc[nt][0] *= fac0; Oacc[nt][1] *= fac0;
            Oacc[nt][2] *= fac1; Oacc[nt][3] *= fac1;
        }
        // ---- paired bf16 exp + P@V (l accumulates in column 96) ----
#pragma unroll
        for (int ks = 0; ks < 4; ks++) {
            unsigned pa[4];
            pa[0] = bex2(pk(sacc[2 * ks][0] - mn0,     sacc[2 * ks][1] - mn0));
            pa[1] = bex2(pk(sacc[2 * ks][2] - mn1,     sacc[2 * ks][3] - mn1));
            pa[2] = bex2(pk(sacc[2 * ks + 1][0] - mn0, sacc[2 * ks + 1][1] - mn0));
            pa[3] = bex2(pk(sacc[2 * ks + 1][2] - mn1, sacc[2 * ks + 1][3] - mn1));
#pragma unroll
            for (int nt = 0; nt < 13; nt++) {
                uint2 vb2 = *(const uint2*)&Vs[((ks * 13 + nt) * 32 + lane) * 2];
                mma_bf16(Oacc[nt], pa, (const unsigned*)&vb2);
            }
        }
        __syncthreads();
    }

    // ---- epilogue: l lives in col 96 of the quad leader ----
    float l0 = __shfl_sync(0xffffffffu, Oacc[12][0], lane & 28);
    float l1 = __shfl_sync(0xffffffffu, Oacc[12][2], lane & 28);
    float inv0 = 1.0f / l0;
    float inv1 = 1.0f / l1;
#pragma unroll
    for (int nt = 0; nt < 12; nt++) {
        int col = h * DH_ + nt * 8 + c2;
        *(unsigned*)(out + ((size_t)b * LM_ + q0 + r0) * H_ + col) =
            pk(Oacc[nt][0] * inv0, Oacc[nt][1] * inv0);
        *(unsigned*)(out + ((size_t)b * LM_ + q0 + r0 + 8) * H_ + col) =
            pk(Oacc[nt][2] * inv1, Oacc[nt][3] * inv1);
    }
}

// ---------------- masked mean-pool ----------------
__global__ __launch_bounds__(256) void pool_kernel(
    const float* __restrict__ hidden, const float* __restrict__ oproj,
    const int* __restrict__ line_starts, const int* __restrict__ line_lens,
    float* __restrict__ x)
{
    int bl = blockIdx.x;
    int b = bl / L_;
    int len = line_lens[bl];
    int start = line_starts[bl];
    float inv = 1.0f / (float)max(len, 1);
    for (int c = threadIdx.x; c < H_; c += 256) {
        float s1 = 0.0f, s2 = 0.0f;
        for (int m = 0; m < ML_; m++) {
            if (m < len) {
                int pos = min(max(start + m, 0), S_ - 1);
                s1 += hidden[((size_t)b * S_ + pos) * H_ + c];
                s2 += oproj[((size_t)bl * ML_ + m) * H_ + c];
            }
        }
        x[(size_t)bl * 2 * H_ + c]      = s1 * inv;
        x[(size_t)bl * 2 * H_ + H_ + c] = s2 * inv;
    }
}

// ---------------- LayerNorm -> exact GELU (+optional residual) ----------------
__global__ __launch_bounds__(256) void ln_gelu_kernel(
    const float* __restrict__ y, const float* __restrict__ g,
    const float* __restrict__ be, const float* __restrict__ res,
    float* __restrict__ out)
{
    __shared__ float red1[8], red2[8];
    int row = blockIdx.x;
    const float* yr = y + (size_t)row * H_;
    float v[3], sum = 0.0f, sq = 0.0f;
#pragma unroll
    for (int i = 0; i < 3; i++) {
        v[i] = yr[threadIdx.x + 256 * i];
        sum += v[i];
        sq  += v[i] * v[i];
    }
#pragma unroll
    for (int o = 16; o > 0; o >>= 1) {
        sum += __shfl_xor_sync(0xffffffffu, sum, o);
        sq  += __shfl_xor_sync(0xffffffffu, sq,  o);
    }
    int warp = threadIdx.x >> 5;
    if ((threadIdx.x & 31) == 0) { red1[warp] = sum; red2[warp] = sq; }
    __syncthreads();
    float tsum = 0.0f, tsq = 0.0f;
#pragma unroll
    for (int i = 0; i < 8; i++) { tsum += red1[i]; tsq += red2[i]; }
    float mean = tsum * (1.0f / H_);
    float var  = tsq  * (1.0f / H_) - mean * mean;
    float rstd = rsqrtf(var + 1e-5f);
#pragma unroll
    for (int i = 0; i < 3; i++) {
        int c = threadIdx.x + 256 * i;
        float t  = (v[i] - mean) * rstd * g[c] + be[c];
        float ge = 0.5f * t * (1.0f + erff(t * 0.70710678118654752f));
        out[(size_t)row * H_ + c] = (res ? res[(size_t)row * H_ + c] : 0.0f) + ge;
    }
}

// ---------------- final logit ----------------
__global__ __launch_bounds__(128) void final_kernel(
    const float* __restrict__ a2, const float* __restrict__ W3,
    const float* __restrict__ b3, const int* __restrict__ line_lens,
    float* __restrict__ out)
{
    int row  = blockIdx.x * 4 + (threadIdx.x >> 5);
    int lane = threadIdx.x & 31;
    float s = 0.0f;
    for (int c = lane; c < H_; c += 32)
        s += a2[(size_t)row * H_ + c] * W3[c];
#pragma unroll
    for (int o = 16; o > 0; o >>= 1) s += __shfl_xor_sync(0xffffffffu, s, o);
    if (lane == 0) {
        float logit = s + b3[0];
        if (line_lens[row] <= 0) logit = -10.0f;
        out[row] = 1.0f / (1.0f + __expf(-logit));
    }
}

// ---------------- launch ----------------
extern "C" void kernel_launch(void* const* d_in, const int* in_sizes, int n_in,
                              void* d_out, int out_size)
{
    (void)in_sizes; (void)n_in; (void)out_size;
    const float* hidden  = (const float*)d_in[0];
    const float* in_w    = (const float*)d_in[1];
    const float* in_b    = (const float*)d_in[2];
    const float* out_w   = (const float*)d_in[3];
    const float* out_b   = (const float*)d_in[4];
    const float* W1      = (const float*)d_in[5];
    const float* b1      = (const float*)d_in[6];
    const float* g1      = (const float*)d_in[7];
    const float* be1     = (const float*)d_in[8];
    const float* W2      = (const float*)d_in[9];
    const float* b2      = (const float*)d_in[10];
    const float* g2      = (const float*)d_in[11];
    const float* be2     = (const float*)d_in[12];
    const float* W3      = (const float*)d_in[13];
    const float* b3      = (const float*)d_in[14];
    const int*   lstarts = (const int*)d_in[15];
    const int*   llens   = (const int*)d_in[16];
    const int*   ctx     = (const int*)d_in[17];
    float* out = (float*)d_out;

    __nv_bfloat16 *hb, *wib, *wob, *qkvh, *atnh;
    float *oproj, *x, *y1, *y2;
    cudaGetSymbolAddress((void**)&hb,    g_hb);
    cudaGetSymbolAddress((void**)&wib,   g_wib);
    cudaGetSymbolAddress((void**)&wob,   g_wob);
    cudaGetSymbolAddress((void**)&qkvh,  g_qkvh);
    cudaGetSymbolAddress((void**)&atnh,  g_atnh);
    cudaGetSymbolAddress((void**)&oproj, g_oproj);
    cudaGetSymbolAddress((void**)&x,     g_x);
    cudaGetSymbolAddress((void**)&y1,    g_y1);
    cudaGetSymbolAddress((void**)&y2,    g_y2);

    const float qmul = 0.10206207261596577f * 1.4426950408889634f;  // 1/sqrt(96)*log2e

    // 0) one-time f32->bf16 converts
    f2b_kernel<<<2048, 256>>>(hidden, hb,  (B_ * S_ * H_) / 2);
    f2b_kernel<<<1024, 256>>>(in_w,  wib, (QKV_ * H_) / 2);
    f2b_kernel<<<512,  256>>>(out_w, wob, (H_ * H_) / 2);

    // 1) QKV projection (bf16 out, Q columns pre-scaled)
    gemm_bf16_cp<<<dim3(QKV_ / 128, (B_ * S_) / 128), 256>>>(
        hb, wib, in_b, qkvh, B_ * S_, QKV_, H_, 1, qmul, H_);
    // 2) cross attention
    attn_kernel<<<dim3(LM_ / 128, NH_, B_), 256>>>(qkvh, lstarts, ctx, atnh);
    // 3) out_proj (bf16 in, f32 out)
    gemm_bf16_cp<<<dim3(H_ / 128, (B_ * LM_) / 128), 256>>>(
        atnh, wob, out_b, oproj, B_ * LM_, H_, H_, 0, 1.0f, 0);
    // 4) pooled features
    pool_kernel<<<B_ * L_, 256>>>(hidden, oproj, lstarts, llens, x);
    // 5) classifier head (tf32)
    gemm_tf32_nt<<<dim3(H_ / 128, (B_ * L_) / 128), 256>>>(x, W1, b1, y1, B_ * L_, H_, 2 * H_);
    ln_gelu_kernel<<<B_ * L_, 256>>>(y1, g1, be1, nullptr, y1);
    gemm_tf32_nt<<<dim3(H_ / 128, (B_ * L_) / 128), 256>>>(y1, W2, b2, y2, B_ * L_, H_, H_);
    ln_gelu_kernel<<<B_ * L_, 256>>>(y2, g2, be2, y1, y2);
    final_kernel<<<B_ * L_ / 4, 128>>>(y2, W3, b3, llens, out);
}

// round 10
// speedup vs baseline: 7.5727x; 1.3026x over previous
#include <cuda_runtime.h>
#include <cuda_bf16.h>
#include <math.h>
#include <stdint.h>

// ---------------- problem constants ----------------
#define B_    4
#define S_    2048
#define H_    768
#define NH_   8
#define DH_   96
#define L_    128
#define ML_   15
#define LM_   1920      // L_*ML_
#define QKV_  2304      // 3*H_

// ---------------- scratch ----------------
__device__ __nv_bfloat16 g_hb  [(size_t)B_ * S_ * H_];
__device__ __nv_bfloat16 g_wib [(size_t)QKV_ * H_];
__device__ __nv_bfloat16 g_wob [(size_t)H_ * H_];
__device__ __nv_bfloat16 g_qkvh[(size_t)B_ * S_ * QKV_];   // Q pre-scaled
__device__ __nv_bfloat16 g_atnh[(size_t)B_ * LM_ * H_];
__device__ float g_oproj[(size_t)B_ * LM_ * H_];
__device__ float g_x    [(size_t)B_ * L_ * 2 * H_];
__device__ float g_y1   [(size_t)B_ * L_ * H_];
__device__ float g_y2   [(size_t)B_ * L_ * H_];

// ---------------- helpers ----------------
__device__ __forceinline__ unsigned pk(float lo, float hi) {
    unsigned r;
    asm("cvt.rn.bf16x2.f32 %0, %1, %2;" : "=r"(r) : "f"(hi), "f"(lo));
    return r;
}
__device__ __forceinline__ float ex2(float x) {
    float r;
    asm("ex2.approx.ftz.f32 %0, %1;" : "=f"(r) : "f"(x));
    return r;
}
__device__ __forceinline__ unsigned bex2(unsigned x) {
    unsigned r;
    asm("ex2.approx.ftz.bf16x2 %0, %1;" : "=r"(r) : "r"(x));
    return r;
}
__device__ __forceinline__ void mma_bf16(float* d, const unsigned* a, const unsigned* b) {
    asm volatile(
        "mma.sync.aligned.m16n8k16.row.col.f32.bf16.bf16.f32 "
        "{%0,%1,%2,%3}, {%4,%5,%6,%7}, {%8,%9}, {%0,%1,%2,%3};"
        : "+f"(d[0]), "+f"(d[1]), "+f"(d[2]), "+f"(d[3])
        : "r"(a[0]), "r"(a[1]), "r"(a[2]), "r"(a[3]), "r"(b[0]), "r"(b[1]));
}
__device__ __forceinline__ void mma_tf32(float* d, const unsigned* a, const unsigned* b) {
    asm volatile(
        "mma.sync.aligned.m16n8k8.row.col.f32.tf32.tf32.f32 "
        "{%0,%1,%2,%3}, {%4,%5,%6,%7}, {%8,%9}, {%0,%1,%2,%3};"
        : "+f"(d[0]), "+f"(d[1]), "+f"(d[2]), "+f"(d[3])
        : "r"(a[0]), "r"(a[1]), "r"(a[2]), "r"(a[3]), "r"(b[0]), "r"(b[1]));
}
__device__ __forceinline__ uint32_t s2u(const void* p) {
    uint32_t a;
    asm("{ .reg .u64 t; cvta.to.shared.u64 t, %1; cvt.u32.u64 %0, t; }" : "=r"(a) : "l"(p));
    return a;
}
__device__ __forceinline__ void cpa16(uint32_t s, const void* g) {
    asm volatile("cp.async.cg.shared.global [%0], [%1], 16;" :: "r"(s), "l"(g));
}
#define CP_COMMIT() asm volatile("cp.async.commit_group;")
#define CP_WAIT2()  asm volatile("cp.async.wait_group 2;")
#define CP_WAIT1()  asm volatile("cp.async.wait_group 1;")
__device__ __forceinline__ void ldm4(uint4& d, uint32_t a) {
    asm volatile("ldmatrix.sync.aligned.m8n8.x4.shared.b16 {%0,%1,%2,%3}, [%4];"
                 : "=r"(d.x), "=r"(d.y), "=r"(d.z), "=r"(d.w) : "r"(a));
}
__device__ __forceinline__ void ldm4t(uint4& d, uint32_t a) {
    asm volatile("ldmatrix.sync.aligned.m8n8.x4.trans.shared.b16 {%0,%1,%2,%3}, [%4];"
                 : "=r"(d.x), "=r"(d.y), "=r"(d.z), "=r"(d.w) : "r"(a));
}

// ---------------- f32 -> bf16 convert ----------------
__global__ __launch_bounds__(256) void f2b_kernel(
    const float* __restrict__ src, __nv_bfloat16* __restrict__ dst, int n2)
{
    int stride = gridDim.x * blockDim.x;
    for (int i = blockIdx.x * blockDim.x + threadIdx.x; i < n2; i += stride) {
        float2 v = ((const float2*)src)[i];
        ((unsigned*)dst)[i] = pk(v.x, v.y);
    }
}

// ---------------- bf16 NT GEMM: cp.async 3-stage + ldmatrix (unchanged) ----------------
__global__ __launch_bounds__(256) void gemm_bf16_cp(
    const __nv_bfloat16* __restrict__ A, const __nv_bfloat16* __restrict__ Bw,
    const float* __restrict__ bias, void* __restrict__ Cout,
    int M, int N, int K, int out_bf16, float qmul, int qcols)
{
    __shared__ __align__(16) char smem[3 * 16384];

    int tid = threadIdx.x;
    int warp = tid >> 5, lane = tid & 31;
    int warp_m = warp >> 1, warp_n = warp & 1;
    int m0 = blockIdx.y * 128, n0 = blockIdx.x * 128;
    uint32_t sbase = s2u(smem);

    float acc[2][8][4];
#pragma unroll
    for (int mi = 0; mi < 2; mi++)
#pragma unroll
        for (int ni = 0; ni < 8; ni++)
#pragma unroll
            for (int r = 0; r < 4; r++) acc[mi][ni][r] = 0.0f;

    int nslab = K >> 5;
    int frow0 = tid >> 2,        fc0 = tid & 3;
    int frow1 = (tid + 256) >> 2, fc1 = (tid + 256) & 3;

#define FILL(st, sl)                                                                   \
    do {                                                                               \
        int k0f = (sl) << 5;                                                           \
        uint32_t sa = sbase + (st) * 16384;                                            \
        uint32_t sb = sa + 8192;                                                       \
        cpa16(sa + (frow0 * 4 + (fc0 ^ ((frow0 >> 1) & 3))) * 16,                      \
              A + (size_t)(m0 + frow0) * K + k0f + fc0 * 8);                           \
        cpa16(sa + (frow1 * 4 + (fc1 ^ ((frow1 >> 1) & 3))) * 16,                      \
              A + (size_t)(m0 + frow1) * K + k0f + fc1 * 8);                           \
        cpa16(sb + (frow0 * 4 + (fc0 ^ ((frow0 >> 1) & 3))) * 16,                      \
              Bw + (size_t)(n0 + frow0) * K + k0f + fc0 * 8);                          \
        cpa16(sb + (frow1 * 4 + (fc1 ^ ((frow1 >> 1) & 3))) * 16,                      \
              Bw + (size_t)(n0 + frow1) * K + k0f + fc1 * 8);                          \
    } while (0)

    FILL(0, 0); CP_COMMIT();
    if (nslab > 1) FILL(1, 1);
    CP_COMMIT();

    for (int i = 0; i < nslab; i++) {
        if (i + 2 < nslab) FILL((i + 2) % 3, i + 2);
        CP_COMMIT();
        CP_WAIT2();
        __syncthreads();

        uint32_t sa = sbase + (i % 3) * 16384;
        uint32_t sb = sa + 8192;
#pragma unroll
        for (int ks = 0; ks < 2; ks++) {
            uint4 afr[2];
#pragma unroll
            for (int mi = 0; mi < 2; mi++) {
                int row = warp_m * 32 + mi * 16 + ((lane >> 3) & 1) * 8 + (lane & 7);
                int ch = ks * 2 + (lane >> 4);
                ldm4(afr[mi], sa + (row * 4 + (ch ^ ((row >> 1) & 3))) * 16);
            }
            uint4 bfr[4];
#pragma unroll
            for (int nj = 0; nj < 4; nj++) {
                int row = warp_n * 64 + nj * 16 + ((lane >> 4) & 1) * 8 + (lane & 7);
                int ch = ks * 2 + ((lane >> 3) & 1);
                ldm4(bfr[nj], sb + (row * 4 + (ch ^ ((row >> 1) & 3))) * 16);
            }
#pragma unroll
            for (int mi = 0; mi < 2; mi++)
#pragma unroll
                for (int nj = 0; nj < 4; nj++) {
                    mma_bf16(acc[mi][2 * nj],     (const unsigned*)&afr[mi], &bfr[nj].x);
                    mma_bf16(acc[mi][2 * nj + 1], (const unsigned*)&afr[mi], &bfr[nj].z);
                }
        }
        __syncthreads();
    }
#undef FILL

#pragma unroll
    for (int mi = 0; mi < 2; mi++) {
        int row = m0 + warp_m * 32 + mi * 16 + (lane >> 2);
#pragma unroll
        for (int ni = 0; ni < 8; ni++) {
            int col = n0 + warp_n * 64 + ni * 8 + ((lane & 3) << 1);
            float b0 = bias ? bias[col] : 0.0f;
            float b1 = bias ? bias[col + 1] : 0.0f;
            float v0 = acc[mi][ni][0] + b0, v1 = acc[mi][ni][1] + b1;
            float v2 = acc[mi][ni][2] + b0, v3 = acc[mi][ni][3] + b1;
            if (out_bf16) {
                float s = (col < qcols) ? qmul : 1.0f;
                __nv_bfloat16* Cb = (__nv_bfloat16*)Cout;
                *(unsigned*)(Cb + (size_t)row * N + col)       = pk(v0 * s, v1 * s);
                *(unsigned*)(Cb + (size_t)(row + 8) * N + col) = pk(v2 * s, v3 * s);
            } else {
                float* Cf = (float*)Cout;
                *(float2*)(Cf + (size_t)row * N + col)       = make_float2(v0, v1);
                *(float2*)(Cf + (size_t)(row + 8) * N + col) = make_float2(v2, v3);
            }
        }
    }
}

// ---------------- tf32 NT GEMM (classifier, unchanged) ----------------
__global__ __launch_bounds__(256) void gemm_tf32_nt(
    const float* __restrict__ A, const float* __restrict__ Bw,
    const float* __restrict__ bias, float* __restrict__ C,
    int M, int N, int K)
{
    __shared__ unsigned As[4 * 8 * 128];
    __shared__ unsigned Bs[4 * 16 * 64];

    int tid = threadIdx.x;
    int warp = tid >> 5, lane = tid & 31;
    int warp_m = warp >> 1, warp_n = warp & 1;
    int m0 = blockIdx.y * 128, n0 = blockIdx.x * 128;

    float acc[2][8][4];
#pragma unroll
    for (int mi = 0; mi < 2; mi++)
#pragma unroll
        for (int ni = 0; ni < 8; ni++)
#pragma unroll
            for (int r = 0; r < 4; r++) acc[mi][ni][r] = 0.0f;

    for (int k0 = 0; k0 < K; k0 += 32) {
        __syncthreads();
#pragma unroll
        for (int i = 0; i < 4; i++) {
            int f = tid + i * 256;
            int row = f >> 3, kq = f & 7;
            float4 v = *(const float4*)(A + (size_t)(m0 + row) * K + k0 + kq * 4);
            int mtile = row >> 4, r = row & 15, ktile = kq >> 1;
            int regb = (r >> 3) + ((kq & 1) << 1);
            unsigned* p = &As[((ktile * 8 + mtile) * 32 + (r & 7) * 4) * 4 + regb];
            p[0]  = __float_as_uint(v.x);
            p[4]  = __float_as_uint(v.y);
            p[8]  = __float_as_uint(v.z);
            p[12] = __float_as_uint(v.w);
        }
#pragma unroll
        for (int i = 0; i < 4; i++) {
            int f = tid + i * 256;
            int row = f >> 3, kq = f & 7;
            float4 v = *(const float4*)(Bw + (size_t)(n0 + row) * K + k0 + kq * 4);
            int ntile = row >> 3, ktile = kq >> 1, reg = kq & 1;
            unsigned* p = &Bs[(ktile * 16 + ntile) * 64 + (row & 7) * 8 + reg];
            p[0] = __float_as_uint(v.x);
            p[2] = __float_as_uint(v.y);
            p[4] = __float_as_uint(v.z);
            p[6] = __float_as_uint(v.w);
        }
        __syncthreads();
#pragma unroll
        for (int ks = 0; ks < 4; ks++) {
            uint4 a[2];
            uint2 b[8];
#pragma unroll
            for (int mi = 0; mi < 2; mi++)
                a[mi] = *(const uint4*)&As[((ks * 8 + warp_m * 2 + mi) * 32 + lane) * 4];
#pragma unroll
            for (int ni = 0; ni < 8; ni++)
                b[ni] = *(const uint2*)&Bs[((ks * 16 + warp_n * 8 + ni) * 32 + lane) * 2];
#pragma unroll
            for (int mi = 0; mi < 2; mi++)
#pragma unroll
                for (int ni = 0; ni < 8; ni++)
                    mma_tf32(acc[mi][ni], (const unsigned*)&a[mi], (const unsigned*)&b[ni]);
        }
    }

#pragma unroll
    for (int mi = 0; mi < 2; mi++) {
        int row = m0 + warp_m * 32 + mi * 16 + (lane >> 2);
#pragma unroll
        for (int ni = 0; ni < 8; ni++) {
            int col = n0 + warp_n * 64 + ni * 8 + ((lane & 3) << 1);
            float b0 = bias ? bias[col] : 0.0f;
            float b1 = bias ? bias[col + 1] : 0.0f;
            *(float2*)(C + (size_t)row * N + col)       = make_float2(acc[mi][ni][0] + b0, acc[mi][ni][1] + b1);
            *(float2*)(C + (size_t)(row + 8) * N + col) = make_float2(acc[mi][ni][2] + b0, acc[mi][ni][3] + b1);
        }
    }
}

// ---------------- bf16 flash cross-attention: cp.async 2-stage + ldmatrix ----------------
// K,V raw row-major [64 tok][192B] per stage, swizzled; l via ones B-frag mma.
#define AST 24576   // per-stage: K 12288 + V 12288
__global__ __launch_bounds__(256, 2) void attn_kernel(
    const __nv_bfloat16* __restrict__ qkv,
    const int* __restrict__ line_starts,
    const int* __restrict__ ctx_len,
    __nv_bfloat16* __restrict__ out)
{
    __shared__ __align__(16) char smem[2 * AST];   // 48KB

    int tid = threadIdx.x;
    int warp = tid >> 5, lane = tid & 31;
    int b = blockIdx.z, h = blockIdx.y, q0 = blockIdx.x * 128;
    uint32_t sb = s2u(smem);

    int r0 = warp * 16 + (lane >> 2);
    int c2 = (lane & 3) * 2;
    int ctx = ctx_len[b];

    // ---- Q fragments straight from gmem (bf16, pre-scaled) ----
    const __nv_bfloat16 *qp0, *qp1;
    {
        int gq0 = q0 + r0;
        int l0i = gq0 / ML_, mm0 = gq0 - l0i * ML_;
        int pos0 = min(max(line_starts[b * L_ + l0i] + mm0, 0), S_ - 1);
        int gq1 = gq0 + 8;
        int l1i = gq1 / ML_, mm1 = gq1 - l1i * ML_;
        int pos1 = min(max(line_starts[b * L_ + l1i] + mm1, 0), S_ - 1);
        qp0 = qkv + ((size_t)b * S_ + pos0) * QKV_ + h * DH_;
        qp1 = qkv + ((size_t)b * S_ + pos1) * QKV_ + h * DH_;
    }
    unsigned qf[6][4];
#pragma unroll
    for (int ks = 0; ks < 6; ks++) {
        qf[ks][0] = *(const unsigned*)(qp0 + ks * 16 + c2);
        qf[ks][1] = *(const unsigned*)(qp1 + ks * 16 + c2);
        qf[ks][2] = *(const unsigned*)(qp0 + ks * 16 + c2 + 8);
        qf[ks][3] = *(const unsigned*)(qp1 + ks * 16 + c2 + 8);
    }

    // ---- per-thread fill coords: 768 chunks per matrix / 256 thr = 3 each ----
    const __nv_bfloat16 *kg[3], *vg[3];
    int foff[3];
#pragma unroll
    for (int i = 0; i < 3; i++) {
        int u = tid + i * 256;
        int row = u / 12, c = u - row * 12;
        foff[i] = row * 192 + (c ^ ((row >> 1) & 3)) * 16;
        kg[i] = qkv + ((size_t)b * S_ + row) * QKV_ + H_ + h * DH_ + c * 8;
        vg[i] = kg[i] + H_;
    }

    // ---- per-thread ldmatrix coords ----
    // scores (K, non-trans): matrix m=lane>>3: rows ntp*16+(m>>1)*8+(lane&7), chunk 2*ks+(m&1)
    int sm = lane >> 3;
    int srow = (sm >> 1) * 8 + (lane & 7);
    int scb = sm & 1;
    int sprow[4], spsw[4];
#pragma unroll
    for (int np = 0; np < 4; np++) {
        int row = np * 16 + srow;
        sprow[np] = row * 192;
        spsw[np] = (row >> 1) & 3;
    }
    // PV (V, trans): matrix m: rows ks*16+(m&1)*8+(lane&7), chunk 2*ntp+(m>>1)
    int vrow_b = (sm & 1) * 8 + (lane & 7);
    int vcb = sm >> 1;
    int vprow[4], vpsw[4];
#pragma unroll
    for (int ks = 0; ks < 4; ks++) {
        int row = ks * 16 + vrow_b;
        vprow[ks] = row * 192;
        vpsw[ks] = (row >> 1) & 3;
    }

    const unsigned bones[2] = {0x3F803F80u, 0x3F803F80u};

    float m0 = -1e30f, m1 = -1e30f;
    float Oacc[12][4], lacc[4];
#pragma unroll
    for (int nt = 0; nt < 12; nt++)
#pragma unroll
        for (int r = 0; r < 4; r++) Oacc[nt][r] = 0.0f;
#pragma unroll
    for (int r = 0; r < 4; r++) lacc[r] = 0.0f;

#define AFILL(st, s0f)                                                          \
    do {                                                                        \
        uint32_t kb_ = sb + (st) * AST;                                         \
        uint32_t vb_ = kb_ + 12288;                                             \
        _Pragma("unroll")                                                       \
        for (int i_ = 0; i_ < 3; i_++) {                                        \
            cpa16(kb_ + foff[i_], kg[i_] + (size_t)(s0f) * QKV_);               \
            cpa16(vb_ + foff[i_], vg[i_] + (size_t)(s0f) * QKV_);               \
        }                                                                       \
    } while (0)

    AFILL(0, 0); CP_COMMIT();

    for (int ci = 0; ci < 32; ci++) {
        int s0 = ci * 64;
        if (ci < 31) AFILL((ci + 1) & 1, s0 + 64);
        CP_COMMIT();
        CP_WAIT1();
        __syncthreads();

        uint32_t Kst = sb + (ci & 1) * AST;
        uint32_t Vst = Kst + 12288;

        // ---- scores: 16q x 64tok per warp ----
        float sacc[8][4];
#pragma unroll
        for (int nt = 0; nt < 8; nt++)
#pragma unroll
            for (int r = 0; r < 4; r++) sacc[nt][r] = 0.0f;
#pragma unroll
        for (int ks = 0; ks < 6; ks++) {
#pragma unroll
            for (int np = 0; np < 4; np++) {
                uint4 kb;
                ldm4(kb, Kst + sprow[np] + ((2 * ks + scb) ^ spsw[np]) * 16);
                mma_bf16(sacc[2 * np],     qf[ks], &kb.x);
                mma_bf16(sacc[2 * np + 1], qf[ks], &kb.z);
            }
        }

        // ---- mask + running max ----
        float mx0 = -3e38f, mx1 = -3e38f;
#pragma unroll
        for (int nt = 0; nt < 8; nt++) {
            int t = s0 + nt * 8 + c2;
            if (t >= ctx)     { sacc[nt][0] = -3e38f; sacc[nt][2] = -3e38f; }
            if (t + 1 >= ctx) { sacc[nt][1] = -3e38f; sacc[nt][3] = -3e38f; }
            mx0 = fmaxf(mx0, fmaxf(sacc[nt][0], sacc[nt][1]));
            mx1 = fmaxf(mx1, fmaxf(sacc[nt][2], sacc[nt][3]));
        }
        mx0 = fmaxf(mx0, __shfl_xor_sync(0xffffffffu, mx0, 1));
        mx0 = fmaxf(mx0, __shfl_xor_sync(0xffffffffu, mx0, 2));
        mx1 = fmaxf(mx1, __shfl_xor_sync(0xffffffffu, mx1, 1));
        mx1 = fmaxf(mx1, __shfl_xor_sync(0xffffffffu, mx1, 2));
        float mn0 = fmaxf(m0, mx0), mn1 = fmaxf(m1, mx1);
        float fac0 = ex2(m0 - mn0), fac1 = ex2(m1 - mn1);
        m0 = mn0; m1 = mn1;

        // ---- rescale O and l ----
#pragma unroll
        for (int nt = 0; nt < 12; nt++) {
            Oacc[nt][0] *= fac0; Oacc[nt][1] *= fac0;
            Oacc[nt][2] *= fac1; Oacc[nt][3] *= fac1;
        }
        lacc[0] *= fac0; lacc[1] *= fac0; lacc[2] *= fac1; lacc[3] *= fac1;

        // ---- paired bf16 exp + P@V (+ l via ones frag) ----
#pragma unroll
        for (int ks = 0; ks < 4; ks++) {
            unsigned pa[4];
            pa[0] = bex2(pk(sacc[2 * ks][0] - mn0,     sacc[2 * ks][1] - mn0));
            pa[1] = bex2(pk(sacc[2 * ks][2] - mn1,     sacc[2 * ks][3] - mn1));
            pa[2] = bex2(pk(sacc[2 * ks + 1][0] - mn0, sacc[2 * ks + 1][1] - mn0));
            pa[3] = bex2(pk(sacc[2 * ks + 1][2] - mn1, sacc[2 * ks + 1][3] - mn1));
            mma_bf16(lacc, pa, bones);
#pragma unroll
            for (int np = 0; np < 6; np++) {
                uint4 vb;
                ldm4t(vb, Vst + vprow[ks] + ((2 * np + vcb) ^ vpsw[ks]) * 16);
                mma_bf16(Oacc[2 * np],     pa, &vb.x);
                mma_bf16(Oacc[2 * np + 1], pa, &vb.z);
            }
        }
        __syncthreads();
    }
#undef AFILL

    // ---- epilogue: l identical across n-columns, no shuffles needed ----
    float inv0 = 1.0f / lacc[0];
    float inv1 = 1.0f / lacc[2];
#pragma unroll
    for (int nt = 0; nt < 12; nt++) {
        int col = h * DH_ + nt * 8 + c2;
        *(unsigned*)(out + ((size_t)b * LM_ + q0 + r0) * H_ + col) =
            pk(Oacc[nt][0] * inv0, Oacc[nt][1] * inv0);
        *(unsigned*)(out + ((size_t)b * LM_ + q0 + r0 + 8) * H_ + col) =
            pk(Oacc[nt][2] * inv1, Oacc[nt][3] * inv1);
    }
}

// ---------------- masked mean-pool ----------------
__global__ __launch_bounds__(256) void pool_kernel(
    const float* __restrict__ hidden, const float* __restrict__ oproj,
    const int* __restrict__ line_starts, const int* __restrict__ line_lens,
    float* __restrict__ x)
{
    int bl = blockIdx.x;
    int b = bl / L_;
    int len = line_lens[bl];
    int start = line_starts[bl];
    float inv = 1.0f / (float)max(len, 1);
    for (int c = threadIdx.x; c < H_; c += 256) {
        float s1 = 0.0f, s2 = 0.0f;
        for (int m = 0; m < ML_; m++) {
            if (m < len) {
                int pos = min(max(start + m, 0), S_ - 1);
                s1 += hidden[((size_t)b * S_ + pos) * H_ + c];
                s2 += oproj[((size_t)bl * ML_ + m) * H_ + c];
            }
        }
        x[(size_t)bl * 2 * H_ + c]      = s1 * inv;
        x[(size_t)bl * 2 * H_ + H_ + c] = s2 * inv;
    }
}

// ---------------- LayerNorm -> exact GELU (+optional residual) ----------------
__global__ __launch_bounds__(256) void ln_gelu_kernel(
    const float* __restrict__ y, const float* __restrict__ g,
    const float* __restrict__ be, const float* __restrict__ res,
    float* __restrict__ out)
{
    __shared__ float red1[8], red2[8];
    int row = blockIdx.x;
    const float* yr = y + (size_t)row * H_;
    float v[3], sum = 0.0f, sq = 0.0f;
#pragma unroll
    for (int i = 0; i < 3; i++) {
        v[i] = yr[threadIdx.x + 256 * i];
        sum += v[i];
        sq  += v[i] * v[i];
    }
#pragma unroll
    for (int o = 16; o > 0; o >>= 1) {
        sum += __shfl_xor_sync(0xffffffffu, sum, o);
        sq  += __shfl_xor_sync(0xffffffffu, sq,  o);
    }
    int warp = threadIdx.x >> 5;
    if ((threadIdx.x & 31) == 0) { red1[warp] = sum; red2[warp] = sq; }
    __syncthreads();
    float tsum = 0.0f, tsq = 0.0f;
#pragma unroll
    for (int i = 0; i < 8; i++) { tsum += red1[i]; tsq += red2[i]; }
    float mean = tsum * (1.0f / H_);
    float var  = tsq  * (1.0f / H_) - mean * mean;
    float rstd = rsqrtf(var + 1e-5f);
#pragma unroll
    for (int i = 0; i < 3; i++) {
        int c = threadIdx.x + 256 * i;
        float t  = (v[i] - mean) * rstd * g[c] + be[c];
        float ge = 0.5f * t * (1.0f + erff(t * 0.70710678118654752f));
        out[(size_t)row * H_ + c] = (res ? res[(size_t)row * H_ + c] : 0.0f) + ge;
    }
}

// ---------------- final logit ----------------
__global__ __launch_bounds__(128) void final_kernel(
    const float* __restrict__ a2, const float* __restrict__ W3,
    const float* __restrict__ b3, const int* __restrict__ line_lens,
    float* __restrict__ out)
{
    int row  = blockIdx.x * 4 + (threadIdx.x >> 5);
    int lane = threadIdx.x & 31;
    float s = 0.0f;
    for (int c = lane; c < H_; c += 32)
        s += a2[(size_t)row * H_ + c] * W3[c];
#pragma unroll
    for (int o = 16; o > 0; o >>= 1) s += __shfl_xor_sync(0xffffffffu, s, o);
    if (lane == 0) {
        float logit = s + b3[0];
        if (line_lens[row] <= 0) logit = -10.0f;
        out[row] = 1.0f / (1.0f + __expf(-logit));
    }
}

// ---------------- launch ----------------
extern "C" void kernel_launch(void* const* d_in, const int* in_sizes, int n_in,
                              void* d_out, int out_size)
{
    (void)in_sizes; (void)n_in; (void)out_size;
    const float* hidden  = (const float*)d_in[0];
    const float* in_w    = (const float*)d_in[1];
    const float* in_b    = (const float*)d_in[2];
    const float* out_w   = (const float*)d_in[3];
    const float* out_b   = (const float*)d_in[4];
    const float* W1      = (const float*)d_in[5];
    const float* b1      = (const float*)d_in[6];
    const float* g1      = (const float*)d_in[7];
    const float* be1     = (const float*)d_in[8];
    const float* W2      = (const float*)d_in[9];
    const float* b2      = (const float*)d_in[10];
    const float* g2      = (const float*)d_in[11];
    const float* be2     = (const float*)d_in[12];
    const float* W3      = (const float*)d_in[13];
    const float* b3      = (const float*)d_in[14];
    const int*   lstarts = (const int*)d_in[15];
    const int*   llens   = (const int*)d_in[16];
    const int*   ctx     = (const int*)d_in[17];
    float* out = (float*)d_out;

    __nv_bfloat16 *hb, *wib, *wob, *qkvh, *atnh;
    float *oproj, *x, *y1, *y2;
    cudaGetSymbolAddress((void**)&hb,    g_hb);
    cudaGetSymbolAddress((void**)&wib,   g_wib);
    cudaGetSymbolAddress((void**)&wob,   g_wob);
    cudaGetSymbolAddress((void**)&qkvh,  g_qkvh);
    cudaGetSymbolAddress((void**)&atnh,  g_atnh);
    cudaGetSymbolAddress((void**)&oproj, g_oproj);
    cudaGetSymbolAddress((void**)&x,     g_x);
    cudaGetSymbolAddress((void**)&y1,    g_y1);
    cudaGetSymbolAddress((void**)&y2,    g_y2);

    const float qmul = 0.10206207261596577f * 1.4426950408889634f;  // 1/sqrt(96)*log2e

    // 0) one-time f32->bf16 converts
    f2b_kernel<<<2048, 256>>>(hidden, hb,  (B_ * S_ * H_) / 2);
    f2b_kernel<<<1024, 256>>>(in_w,  wib, (QKV_ * H_) / 2);
    f2b_kernel<<<512,  256>>>(out_w, wob, (H_ * H_) / 2);

    // 1) QKV projection (bf16 out, Q columns pre-scaled)
    gemm_bf16_cp<<<dim3(QKV_ / 128, (B_ * S_) / 128), 256>>>(
        hb, wib, in_b, qkvh, B_ * S_, QKV_, H_, 1, qmul, H_);
    // 2) cross attention (pipelined cp.async + ldmatrix)
    attn_kernel<<<dim3(LM_ / 128, NH_, B_), 256>>>(qkvh, lstarts, ctx, atnh);
    // 3) out_proj (bf16 in, f32 out)
    gemm_bf16_cp<<<dim3(H_ / 128, (B_ * LM_) / 128), 256>>>(
        atnh, wob, out_b, oproj, B_ * LM_, H_, H_, 0, 1.0f, 0);
    // 4) pooled features
    pool_kernel<<<B_ * L_, 256>>>(hidden, oproj, lstarts, llens, x);
    // 5) classifier head (tf32)
    gemm_tf32_nt<<<dim3(H_ / 128, (B_ * L_) / 128), 256>>>(x, W1, b1, y1, B_ * L_, H_, 2 * H_);
    ln_gelu_kernel<<<B_ * L_, 256>>>(y1, g1, be1, nullptr, y1);
    gemm_tf32_nt<<<dim3(H_ / 128, (B_ * L_) / 128), 256>>>(y1, W2, b2, y2, B_ * L_, H_, H_);
    ln_gelu_kernel<<<B_ * L_, 256>>>(y2, g2, be2, y1, y2);
    final_kernel<<<B_ * L_ / 4, 128>>>(y2, W3, b3, llens, out);
}

// round 11
// speedup vs baseline: 7.8266x; 1.0335x over previous
#include <cuda_runtime.h>
#include <cuda_bf16.h>
#include <math.h>
#include <stdint.h>

// ---------------- problem constants ----------------
#define B_    4
#define S_    2048
#define H_    768
#define NH_   8
#define DH_   96
#define L_    128
#define ML_   15
#define LM_   1920      // L_*ML_
#define QKV_  2304      // 3*H_

// ---------------- scratch ----------------
__device__ __nv_bfloat16 g_hb  [(size_t)B_ * S_ * H_];
__device__ __nv_bfloat16 g_wib [(size_t)QKV_ * H_];
__device__ __nv_bfloat16 g_wob [(size_t)H_ * H_];
__device__ __nv_bfloat16 g_qkvh[(size_t)B_ * S_ * QKV_];   // Q pre-scaled
__device__ __nv_bfloat16 g_atnh[(size_t)B_ * LM_ * H_];
__device__ float g_oproj[(size_t)B_ * LM_ * H_];
__device__ float g_x    [(size_t)B_ * L_ * 2 * H_];
__device__ float g_y1   [(size_t)B_ * L_ * H_];
__device__ float g_y2   [(size_t)B_ * L_ * H_];

// ---------------- helpers ----------------
__device__ __forceinline__ unsigned pk(float lo, float hi) {
    unsigned r;
    asm("cvt.rn.bf16x2.f32 %0, %1, %2;" : "=r"(r) : "f"(hi), "f"(lo));
    return r;
}
__device__ __forceinline__ unsigned bex2(unsigned x) {
    unsigned r;
    asm("ex2.approx.ftz.bf16x2 %0, %1;" : "=r"(r) : "r"(x));
    return r;
}
__device__ __forceinline__ void mma_bf16(float* d, const unsigned* a, const unsigned* b) {
    asm volatile(
        "mma.sync.aligned.m16n8k16.row.col.f32.bf16.bf16.f32 "
        "{%0,%1,%2,%3}, {%4,%5,%6,%7}, {%8,%9}, {%0,%1,%2,%3};"
        : "+f"(d[0]), "+f"(d[1]), "+f"(d[2]), "+f"(d[3])
        : "r"(a[0]), "r"(a[1]), "r"(a[2]), "r"(a[3]), "r"(b[0]), "r"(b[1]));
}
__device__ __forceinline__ void mma_tf32(float* d, const unsigned* a, const unsigned* b) {
    asm volatile(
        "mma.sync.aligned.m16n8k8.row.col.f32.tf32.tf32.f32 "
        "{%0,%1,%2,%3}, {%4,%5,%6,%7}, {%8,%9}, {%0,%1,%2,%3};"
        : "+f"(d[0]), "+f"(d[1]), "+f"(d[2]), "+f"(d[3])
        : "r"(a[0]), "r"(a[1]), "r"(a[2]), "r"(a[3]), "r"(b[0]), "r"(b[1]));
}
__device__ __forceinline__ uint32_t s2u(const void* p) {
    uint32_t a;
    asm("{ .reg .u64 t; cvta.to.shared.u64 t, %1; cvt.u32.u64 %0, t; }" : "=r"(a) : "l"(p));
    return a;
}
__device__ __forceinline__ void cpa16(uint32_t s, const void* g) {
    asm volatile("cp.async.cg.shared.global [%0], [%1], 16;" :: "r"(s), "l"(g));
}
#define CP_COMMIT() asm volatile("cp.async.commit_group;")
#define CP_WAIT2()  asm volatile("cp.async.wait_group 2;")
#define CP_WAIT1()  asm volatile("cp.async.wait_group 1;")
__device__ __forceinline__ void ldm4(uint4& d, uint32_t a) {
    asm volatile("ldmatrix.sync.aligned.m8n8.x4.shared.b16 {%0,%1,%2,%3}, [%4];"
                 : "=r"(d.x), "=r"(d.y), "=r"(d.z), "=r"(d.w) : "r"(a));
}
__device__ __forceinline__ void ldm4t(uint4& d, uint32_t a) {
    asm volatile("ldmatrix.sync.aligned.m8n8.x4.trans.shared.b16 {%0,%1,%2,%3}, [%4];"
                 : "=r"(d.x), "=r"(d.y), "=r"(d.z), "=r"(d.w) : "r"(a));
}

// ---------------- f32 -> bf16 convert ----------------
__global__ __launch_bounds__(256) void f2b_kernel(
    const float* __restrict__ src, __nv_bfloat16* __restrict__ dst, int n2)
{
    int stride = gridDim.x * blockDim.x;
    for (int i = blockIdx.x * blockDim.x + threadIdx.x; i < n2; i += stride) {
        float2 v = ((const float2*)src)[i];
        ((unsigned*)dst)[i] = pk(v.x, v.y);
    }
}

// ---------------- bf16 NT GEMM: cp.async 3-stage + ldmatrix ----------------
__global__ __launch_bounds__(256) void gemm_bf16_cp(
    const __nv_bfloat16* __restrict__ A, const __nv_bfloat16* __restrict__ Bw,
    const float* __restrict__ bias, void* __restrict__ Cout,
    int M, int N, int K, int out_bf16, float qmul, int qcols)
{
    __shared__ __align__(16) char smem[3 * 16384];

    int tid = threadIdx.x;
    int warp = tid >> 5, lane = tid & 31;
    int warp_m = warp >> 1, warp_n = warp & 1;
    int m0 = blockIdx.y * 128, n0 = blockIdx.x * 128;
    uint32_t sbase = s2u(smem);

    float acc[2][8][4];
#pragma unroll
    for (int mi = 0; mi < 2; mi++)
#pragma unroll
        for (int ni = 0; ni < 8; ni++)
#pragma unroll
            for (int r = 0; r < 4; r++) acc[mi][ni][r] = 0.0f;

    int nslab = K >> 5;
    int frow0 = tid >> 2,        fc0 = tid & 3;
    int frow1 = (tid + 256) >> 2, fc1 = (tid + 256) & 3;

#define FILL(st, sl)                                                                   \
    do {                                                                               \
        int k0f = (sl) << 5;                                                           \
        uint32_t sa = sbase + (st) * 16384;                                            \
        uint32_t sb = sa + 8192;                                                       \
        cpa16(sa + (frow0 * 4 + (fc0 ^ ((frow0 >> 1) & 3))) * 16,                      \
              A + (size_t)(m0 + frow0) * K + k0f + fc0 * 8);                           \
        cpa16(sa + (frow1 * 4 + (fc1 ^ ((frow1 >> 1) & 3))) * 16,                      \
              A + (size_t)(m0 + frow1) * K + k0f + fc1 * 8);                           \
        cpa16(sb + (frow0 * 4 + (fc0 ^ ((frow0 >> 1) & 3))) * 16,                      \
              Bw + (size_t)(n0 + frow0) * K + k0f + fc0 * 8);                          \
        cpa16(sb + (frow1 * 4 + (fc1 ^ ((frow1 >> 1) & 3))) * 16,                      \
              Bw + (size_t)(n0 + frow1) * K + k0f + fc1 * 8);                          \
    } while (0)

    FILL(0, 0); CP_COMMIT();
    if (nslab > 1) FILL(1, 1);
    CP_COMMIT();

    for (int i = 0; i < nslab; i++) {
        if (i + 2 < nslab) FILL((i + 2) % 3, i + 2);
        CP_COMMIT();
        CP_WAIT2();
        __syncthreads();

        uint32_t sa = sbase + (i % 3) * 16384;
        uint32_t sb = sa + 8192;
#pragma unroll
        for (int ks = 0; ks < 2; ks++) {
            uint4 afr[2];
#pragma unroll
            for (int mi = 0; mi < 2; mi++) {
                int row = warp_m * 32 + mi * 16 + ((lane >> 3) & 1) * 8 + (lane & 7);
                int ch = ks * 2 + (lane >> 4);
                ldm4(afr[mi], sa + (row * 4 + (ch ^ ((row >> 1) & 3))) * 16);
            }
            uint4 bfr[4];
#pragma unroll
            for (int nj = 0; nj < 4; nj++) {
                int row = warp_n * 64 + nj * 16 + ((lane >> 4) & 1) * 8 + (lane & 7);
                int ch = ks * 2 + ((lane >> 3) & 1);
                ldm4(bfr[nj], sb + (row * 4 + (ch ^ ((row >> 1) & 3))) * 16);
            }
#pragma unroll
            for (int mi = 0; mi < 2; mi++)
#pragma unroll
                for (int nj = 0; nj < 4; nj++) {
                    mma_bf16(acc[mi][2 * nj],     (const unsigned*)&afr[mi], &bfr[nj].x);
                    mma_bf16(acc[mi][2 * nj + 1], (const unsigned*)&afr[mi], &bfr[nj].z);
                }
        }
        __syncthreads();
    }
#undef FILL

#pragma unroll
    for (int mi = 0; mi < 2; mi++) {
        int row = m0 + warp_m * 32 + mi * 16 + (lane >> 2);
#pragma unroll
        for (int ni = 0; ni < 8; ni++) {
            int col = n0 + warp_n * 64 + ni * 8 + ((lane & 3) << 1);
            float b0 = bias ? bias[col] : 0.0f;
            float b1 = bias ? bias[col + 1] : 0.0f;
            float v0 = acc[mi][ni][0] + b0, v1 = acc[mi][ni][1] + b1;
            float v2 = acc[mi][ni][2] + b0, v3 = acc[mi][ni][3] + b1;
            if (out_bf16) {
                float s = (col < qcols) ? qmul : 1.0f;
                __nv_bfloat16* Cb = (__nv_bfloat16*)Cout;
                *(unsigned*)(Cb + (size_t)row * N + col)       = pk(v0 * s, v1 * s);
                *(unsigned*)(Cb + (size_t)(row + 8) * N + col) = pk(v2 * s, v3 * s);
            } else {
                float* Cf = (float*)Cout;
                *(float2*)(Cf + (size_t)row * N + col)       = make_float2(v0, v1);
                *(float2*)(Cf + (size_t)(row + 8) * N + col) = make_float2(v2, v3);
            }
        }
    }
}

// ---------------- tf32 NT GEMM (classifier) ----------------
__global__ __launch_bounds__(256) void gemm_tf32_nt(
    const float* __restrict__ A, const float* __restrict__ Bw,
    const float* __restrict__ bias, float* __restrict__ C,
    int M, int N, int K)
{
    __shared__ unsigned As[4 * 8 * 128];
    __shared__ unsigned Bs[4 * 16 * 64];

    int tid = threadIdx.x;
    int warp = tid >> 5, lane = tid & 31;
    int warp_m = warp >> 1, warp_n = warp & 1;
    int m0 = blockIdx.y * 128, n0 = blockIdx.x * 128;

    float acc[2][8][4];
#pragma unroll
    for (int mi = 0; mi < 2; mi++)
#pragma unroll
        for (int ni = 0; ni < 8; ni++)
#pragma unroll
            for (int r = 0; r < 4; r++) acc[mi][ni][r] = 0.0f;

    for (int k0 = 0; k0 < K; k0 += 32) {
        __syncthreads();
#pragma unroll
        for (int i = 0; i < 4; i++) {
            int f = tid + i * 256;
            int row = f >> 3, kq = f & 7;
            float4 v = *(const float4*)(A + (size_t)(m0 + row) * K + k0 + kq * 4);
            int mtile = row >> 4, r = row & 15, ktile = kq >> 1;
            int regb = (r >> 3) + ((kq & 1) << 1);
            unsigned* p = &As[((ktile * 8 + mtile) * 32 + (r & 7) * 4) * 4 + regb];
            p[0]  = __float_as_uint(v.x);
            p[4]  = __float_as_uint(v.y);
            p[8]  = __float_as_uint(v.z);
            p[12] = __float_as_uint(v.w);
        }
#pragma unroll
        for (int i = 0; i < 4; i++) {
            int f = tid + i * 256;
            int row = f >> 3, kq = f & 7;
            float4 v = *(const float4*)(Bw + (size_t)(n0 + row) * K + k0 + kq * 4);
            int ntile = row >> 3, ktile = kq >> 1, reg = kq & 1;
            unsigned* p = &Bs[(ktile * 16 + ntile) * 64 + (row & 7) * 8 + reg];
            p[0] = __float_as_uint(v.x);
            p[2] = __float_as_uint(v.y);
            p[4] = __float_as_uint(v.z);
            p[6] = __float_as_uint(v.w);
        }
        __syncthreads();
#pragma unroll
        for (int ks = 0; ks < 4; ks++) {
            uint4 a[2];
            uint2 b[8];
#pragma unroll
            for (int mi = 0; mi < 2; mi++)
                a[mi] = *(const uint4*)&As[((ks * 8 + warp_m * 2 + mi) * 32 + lane) * 4];
#pragma unroll
            for (int ni = 0; ni < 8; ni++)
                b[ni] = *(const uint2*)&Bs[((ks * 16 + warp_n * 8 + ni) * 32 + lane) * 2];
#pragma unroll
            for (int mi = 0; mi < 2; mi++)
#pragma unroll
                for (int ni = 0; ni < 8; ni++)
                    mma_tf32(acc[mi][ni], (const unsigned*)&a[mi], (const unsigned*)&b[ni]);
        }
    }

#pragma unroll
    for (int mi = 0; mi < 2; mi++) {
        int row = m0 + warp_m * 32 + mi * 16 + (lane >> 2);
#pragma unroll
        for (int ni = 0; ni < 8; ni++) {
            int col = n0 + warp_n * 64 + ni * 8 + ((lane & 3) << 1);
            float b0 = bias ? bias[col] : 0.0f;
            float b1 = bias ? bias[col + 1] : 0.0f;
            *(float2*)(C + (size_t)row * N + col)       = make_float2(acc[mi][ni][0] + b0, acc[mi][ni][1] + b1);
            *(float2*)(C + (size_t)(row + 8) * N + col) = make_float2(acc[mi][ni][2] + b0, acc[mi][ni][3] + b1);
        }
    }
}

// ---------------- bf16 flash cross-attention: fixed-base softmax ----------------
// cp.async 2-stage K/V pipeline + ldmatrix; p = ex2(s) directly (no running max:
// scores are log2-domain and bounded, fp32 accumulation has huge headroom).
#define AST 24576   // per-stage: K 12288 + V 12288
__global__ __launch_bounds__(256, 2) void attn_kernel(
    const __nv_bfloat16* __restrict__ qkv,
    const int* __restrict__ line_starts,
    const int* __restrict__ ctx_len,
    __nv_bfloat16* __restrict__ out)
{
    __shared__ __align__(16) char smem[2 * AST];   // 48KB

    int tid = threadIdx.x;
    int warp = tid >> 5, lane = tid & 31;
    int b = blockIdx.z, h = blockIdx.y, q0 = blockIdx.x * 128;
    uint32_t sb = s2u(smem);

    int r0 = warp * 16 + (lane >> 2);
    int c2 = (lane & 3) * 2;
    int ctx = ctx_len[b];

    // ---- Q fragments straight from gmem (bf16, pre-scaled by scale*log2e) ----
    const __nv_bfloat16 *qp0, *qp1;
    {
        int gq0 = q0 + r0;
        int l0i = gq0 / ML_, mm0 = gq0 - l0i * ML_;
        int pos0 = min(max(line_starts[b * L_ + l0i] + mm0, 0), S_ - 1);
        int gq1 = gq0 + 8;
        int l1i = gq1 / ML_, mm1 = gq1 - l1i * ML_;
        int pos1 = min(max(line_starts[b * L_ + l1i] + mm1, 0), S_ - 1);
        qp0 = qkv + ((size_t)b * S_ + pos0) * QKV_ + h * DH_;
        qp1 = qkv + ((size_t)b * S_ + pos1) * QKV_ + h * DH_;
    }
    unsigned qf[6][4];
#pragma unroll
    for (int ks = 0; ks < 6; ks++) {
        qf[ks][0] = *(const unsigned*)(qp0 + ks * 16 + c2);
        qf[ks][1] = *(const unsigned*)(qp1 + ks * 16 + c2);
        qf[ks][2] = *(const unsigned*)(qp0 + ks * 16 + c2 + 8);
        qf[ks][3] = *(const unsigned*)(qp1 + ks * 16 + c2 + 8);
    }

    // ---- per-thread fill coords ----
    const __nv_bfloat16 *kg[3], *vg[3];
    int foff[3];
#pragma unroll
    for (int i = 0; i < 3; i++) {
        int u = tid + i * 256;
        int row = u / 12, c = u - row * 12;
        foff[i] = row * 192 + (c ^ ((row >> 1) & 3)) * 16;
        kg[i] = qkv + ((size_t)b * S_ + row) * QKV_ + H_ + h * DH_ + c * 8;
        vg[i] = kg[i] + H_;
    }

    // ---- per-thread ldmatrix coords ----
    int sm = lane >> 3;
    int srow = (sm >> 1) * 8 + (lane & 7);
    int scb = sm & 1;
    int sprow[4], spsw[4];
#pragma unroll
    for (int np = 0; np < 4; np++) {
        int row = np * 16 + srow;
        sprow[np] = row * 192;
        spsw[np] = (row >> 1) & 3;
    }
    int vrow_b = (sm & 1) * 8 + (lane & 7);
    int vcb = sm >> 1;
    int vprow[4], vpsw[4];
#pragma unroll
    for (int ks = 0; ks < 4; ks++) {
        int row = ks * 16 + vrow_b;
        vprow[ks] = row * 192;
        vpsw[ks] = (row >> 1) & 3;
    }

    const unsigned bones[2] = {0x3F803F80u, 0x3F803F80u};

    float Oacc[12][4], lacc[4];
#pragma unroll
    for (int nt = 0; nt < 12; nt++)
#pragma unroll
        for (int r = 0; r < 4; r++) Oacc[nt][r] = 0.0f;
#pragma unroll
    for (int r = 0; r < 4; r++) lacc[r] = 0.0f;

#define AFILL(st, s0f)                                                          \
    do {                                                                        \
        uint32_t kb_ = sb + (st) * AST;                                         \
        uint32_t vb_ = kb_ + 12288;                                             \
        _Pragma("unroll")                                                       \
        for (int i_ = 0; i_ < 3; i_++) {                                        \
            cpa16(kb_ + foff[i_], kg[i_] + (size_t)(s0f) * QKV_);               \
            cpa16(vb_ + foff[i_], vg[i_] + (size_t)(s0f) * QKV_);               \
        }                                                                       \
    } while (0)

    AFILL(0, 0); CP_COMMIT();

    for (int ci = 0; ci < 32; ci++) {
        int s0 = ci * 64;
        if (ci < 31) AFILL((ci + 1) & 1, s0 + 64);
        CP_COMMIT();
        CP_WAIT1();
        __syncthreads();

        uint32_t Kst = sb + (ci & 1) * AST;
        uint32_t Vst = Kst + 12288;

        // ---- scores: 16q x 64tok per warp ----
        float sacc[8][4];
#pragma unroll
        for (int nt = 0; nt < 8; nt++)
#pragma unroll
            for (int r = 0; r < 4; r++) sacc[nt][r] = 0.0f;
#pragma unroll
        for (int ks = 0; ks < 6; ks++) {
#pragma unroll
            for (int np = 0; np < 4; np++) {
                uint4 kb;
                ldm4(kb, Kst + sprow[np] + ((2 * ks + scb) ^ spsw[np]) * 16);
                mma_bf16(sacc[2 * np],     qf[ks], &kb.x);
                mma_bf16(sacc[2 * np + 1], qf[ks], &kb.z);
            }
        }

        // ---- mask only boundary chunks (uniform branch) ----
        if (s0 + 64 > ctx) {
#pragma unroll
            for (int nt = 0; nt < 8; nt++) {
                int t = s0 + nt * 8 + c2;
                if (t >= ctx)     { sacc[nt][0] = -3e38f; sacc[nt][2] = -3e38f; }
                if (t + 1 >= ctx) { sacc[nt][1] = -3e38f; sacc[nt][3] = -3e38f; }
            }
        }

        // ---- fixed-base exp + P@V (+ l via ones frag) ----
#pragma unroll
        for (int ks = 0; ks < 4; ks++) {
            unsigned pa[4];
            pa[0] = bex2(pk(sacc[2 * ks][0],     sacc[2 * ks][1]));
            pa[1] = bex2(pk(sacc[2 * ks][2],     sacc[2 * ks][3]));
            pa[2] = bex2(pk(sacc[2 * ks + 1][0], sacc[2 * ks + 1][1]));
            pa[3] = bex2(pk(sacc[2 * ks + 1][2], sacc[2 * ks + 1][3]));
            mma_bf16(lacc, pa, bones);
#pragma unroll
            for (int np = 0; np < 6; np++) {
                uint4 vb;
                ldm4t(vb, Vst + vprow[ks] + ((2 * np + vcb) ^ vpsw[ks]) * 16);
                mma_bf16(Oacc[2 * np],     pa, &vb.x);
                mma_bf16(Oacc[2 * np + 1], pa, &vb.z);
            }
        }
        __syncthreads();
    }
#undef AFILL

    // ---- epilogue ----
    float inv0 = 1.0f / lacc[0];
    float inv1 = 1.0f / lacc[2];
#pragma unroll
    for (int nt = 0; nt < 12; nt++) {
        int col = h * DH_ + nt * 8 + c2;
        *(unsigned*)(out + ((size_t)b * LM_ + q0 + r0) * H_ + col) =
            pk(Oacc[nt][0] * inv0, Oacc[nt][1] * inv0);
        *(unsigned*)(out + ((size_t)b * LM_ + q0 + r0 + 8) * H_ + col) =
            pk(Oacc[nt][2] * inv1, Oacc[nt][3] * inv1);
    }
}

// ---------------- masked mean-pool ----------------
__global__ __launch_bounds__(256) void pool_kernel(
    const float* __restrict__ hidden, const float* __restrict__ oproj,
    const int* __restrict__ line_starts, const int* __restrict__ line_lens,
    float* __restrict__ x)
{
    int bl = blockIdx.x;
    int b = bl / L_;
    int len = line_lens[bl];
    int start = line_starts[bl];
    float inv = 1.0f / (float)max(len, 1);
    for (int c = threadIdx.x; c < H_; c += 256) {
        float s1 = 0.0f, s2 = 0.0f;
        for (int m = 0; m < ML_; m++) {
            if (m < len) {
                int pos = min(max(start + m, 0), S_ - 1);
                s1 += hidden[((size_t)b * S_ + pos) * H_ + c];
                s2 += oproj[((size_t)bl * ML_ + m) * H_ + c];
            }
        }
        x[(size_t)bl * 2 * H_ + c]      = s1 * inv;
        x[(size_t)bl * 2 * H_ + H_ + c] = s2 * inv;
    }
}

// ---------------- LayerNorm -> exact GELU (+optional residual) ----------------
__global__ __launch_bounds__(256) void ln_gelu_kernel(
    const float* __restrict__ y, const float* __restrict__ g,
    const float* __restrict__ be, const float* __restrict__ res,
    float* __restrict__ out)
{
    __shared__ float red1[8], red2[8];
    int row = blockIdx.x;
    const float* yr = y + (size_t)row * H_;
    float v[3], sum = 0.0f, sq = 0.0f;
#pragma unroll
    for (int i = 0; i < 3; i++) {
        v[i] = yr[threadIdx.x + 256 * i];
        sum += v[i];
        sq  += v[i] * v[i];
    }
#pragma unroll
    for (int o = 16; o > 0; o >>= 1) {
        sum += __shfl_xor_sync(0xffffffffu, sum, o);
        sq  += __shfl_xor_sync(0xffffffffu, sq,  o);
    }
    int warp = threadIdx.x >> 5;
    if ((threadIdx.x & 31) == 0) { red1[warp] = sum; red2[warp] = sq; }
    __syncthreads();
    float tsum = 0.0f, tsq = 0.0f;
#pragma unroll
    for (int i = 0; i < 8; i++) { tsum += red1[i]; tsq += red2[i]; }
    float mean = tsum * (1.0f / H_);
    float var  = tsq  * (1.0f / H_) - mean * mean;
    float rstd = rsqrtf(var + 1e-5f);
#pragma unroll
    for (int i = 0; i < 3; i++) {
        int c = threadIdx.x + 256 * i;
        float t  = (v[i] - mean) * rstd * g[c] + be[c];
        float ge = 0.5f * t * (1.0f + erff(t * 0.70710678118654752f));
        out[(size_t)row * H_ + c] = (res ? res[(size_t)row * H_ + c] : 0.0f) + ge;
    }
}

// ---------------- final logit ----------------
__global__ __launch_bounds__(128) void final_kernel(
    const float* __restrict__ a2, const float* __restrict__ W3,
    const float* __restrict__ b3, const int* __restrict__ line_lens,
    float* __restrict__ out)
{
    int row  = blockIdx.x * 4 + (threadIdx.x >> 5);
    int lane = threadIdx.x & 31;
    float s = 0.0f;
    for (int c = lane; c < H_; c += 32)
        s += a2[(size_t)row * H_ + c] * W3[c];
#pragma unroll
    for (int o = 16; o > 0; o >>= 1) s += __shfl_xor_sync(0xffffffffu, s, o);
    if (lane == 0) {
        float logit = s + b3[0];
        if (line_lens[row] <= 0) logit = -10.0f;
        out[row] = 1.0f / (1.0f + __expf(-logit));
    }
}

// ---------------- launch ----------------
extern "C" void kernel_launch(void* const* d_in, const int* in_sizes, int n_in,
                              void* d_out, int out_size)
{
    (void)in_sizes; (void)n_in; (void)out_size;
    const float* hidden  = (const float*)d_in[0];
    const float* in_w    = (const float*)d_in[1];
    const float* in_b    = (const float*)d_in[2];
    const float* out_w   = (const float*)d_in[3];
    const float* out_b   = (const float*)d_in[4];
    const float* W1      = (const float*)d_in[5];
    const float* b1      = (const float*)d_in[6];
    const float* g1      = (const float*)d_in[7];
    const float* be1     = (const float*)d_in[8];
    const float* W2      = (const float*)d_in[9];
    const float* b2      = (const float*)d_in[10];
    const float* g2      = (const float*)d_in[11];
    const float* be2     = (const float*)d_in[12];
    const float* W3      = (const float*)d_in[13];
    const float* b3      = (const float*)d_in[14];
    const int*   lstarts = (const int*)d_in[15];
    const int*   llens   = (const int*)d_in[16];
    const int*   ctx     = (const int*)d_in[17];
    float* out = (float*)d_out;

    __nv_bfloat16 *hb, *wib, *wob, *qkvh, *atnh;
    float *oproj, *x, *y1, *y2;
    cudaGetSymbolAddress((void**)&hb,    g_hb);
    cudaGetSymbolAddress((void**)&wib,   g_wib);
    cudaGetSymbolAddress((void**)&wob,   g_wob);
    cudaGetSymbolAddress((void**)&qkvh,  g_qkvh);
    cudaGetSymbolAddress((void**)&atnh,  g_atnh);
    cudaGetSymbolAddress((void**)&oproj, g_oproj);
    cudaGetSymbolAddress((void**)&x,     g_x);
    cudaGetSymbolAddress((void**)&y1,    g_y1);
    cudaGetSymbolAddress((void**)&y2,    g_y2);

    const float qmul = 0.10206207261596577f * 1.4426950408889634f;  // 1/sqrt(96)*log2e

    // 0) one-time f32->bf16 converts
    f2b_kernel<<<2048, 256>>>(hidden, hb,  (B_ * S_ * H_) / 2);
    f2b_kernel<<<1024, 256>>>(in_w,  wib, (QKV_ * H_) / 2);
    f2b_kernel<<<512,  256>>>(out_w, wob, (H_ * H_) / 2);

    // 1) QKV projection (bf16 out, Q columns pre-scaled)
    gemm_bf16_cp<<<dim3(QKV_ / 128, (B_ * S_) / 128), 256>>>(
        hb, wib, in_b, qkvh, B_ * S_, QKV_, H_, 1, qmul, H_);
    // 2) cross attention (fixed-base softmax)
    attn_kernel<<<dim3(LM_ / 128, NH_, B_), 256>>>(qkvh, lstarts, ctx, atnh);
    // 3) out_proj (bf16 in, f32 out)
    gemm_bf16_cp<<<dim3(H_ / 128, (B_ * LM_) / 128), 256>>>(
        atnh, wob, out_b, oproj, B_ * LM_, H_, H_, 0, 1.0f, 0);
    // 4) pooled features
    pool_kernel<<<B_ * L_, 256>>>(hidden, oproj, lstarts, llens, x);
    // 5) classifier head (tf32)
    gemm_tf32_nt<<<dim3(H_ / 128, (B_ * L_) / 128), 256>>>(x, W1, b1, y1, B_ * L_, H_, 2 * H_);
    ln_gelu_kernel<<<B_ * L_, 256>>>(y1, g1, be1, nullptr, y1);
    gemm_tf32_nt<<<dim3(H_ / 128, (B_ * L_) / 128), 256>>>(y1, W2, b2, y2, B_ * L_, H_, H_);
    ln_gelu_kernel<<<B_ * L_, 256>>>(y2, g2, be2, y1, y2);
    final_kernel<<<B_ * L_ / 4, 128>>>(y2, W3, b3, llens, out);
}